// round 3
// baseline (speedup 1.0000x reference)
#include <cuda_runtime.h>
#include <math.h>

#define N_V 10000
#define NSPEC 64
#define IN_DESC 352
#define OUT_DESC 256

// ---------------- scratch (device globals; no allocations allowed) ----------
__device__ float g_acc[N_V * 256];   // pre-BN accumulator (max width 256: fc2)
__device__ float g_h[N_V * 128];     // current activations
__device__ float g_tA[N_V * 64];     // Chebyshev T buffers
__device__ float g_tB[N_V * 64];
__device__ float g_tC[N_V * 64];
__device__ float g_dz[NSPEC * NSPEC];
__device__ float g_scale[256];       // BN fused scale/shift
__device__ float g_shift[256];

// ---------------- small GEMM: C[M,N] = A[M,K] @ B[K,N] (+bias) (+=C) --------
// BM=BN=64, BK=16, 256 threads, 4x4 per thread. K%16==0, N%64==0 assumed.
template<int ACC, int BIAS>
__global__ void gemm_small(const float* __restrict__ A, const float* __restrict__ B,
                           const float* __restrict__ bias, float* __restrict__ C,
                           int M, int Nn, int K) {
    __shared__ float As[16][64];
    __shared__ float Bs[16][64];
    const int tid = threadIdx.x;
    const int ty = tid >> 4, tx = tid & 15;
    const int row0 = blockIdx.y * 64, col0 = blockIdx.x * 64;
    const int arow = tid >> 2, ak = (tid & 3) << 2;
    const int bk = tid >> 4, bcol = (tid & 15) << 2;
    float acc[4][4] = {};
    for (int k0 = 0; k0 < K; k0 += 16) {
        float4 av = make_float4(0.f, 0.f, 0.f, 0.f);
        if (row0 + arow < M)
            av = *(const float4*)(A + (size_t)(row0 + arow) * K + k0 + ak);
        As[ak + 0][arow] = av.x; As[ak + 1][arow] = av.y;
        As[ak + 2][arow] = av.z; As[ak + 3][arow] = av.w;
        float4 bv = *(const float4*)(B + (size_t)(k0 + bk) * Nn + col0 + bcol);
        *(float4*)(&Bs[bk][bcol]) = bv;
        __syncthreads();
        #pragma unroll
        for (int kk = 0; kk < 16; kk++) {
            float a[4], b[4];
            #pragma unroll
            for (int i = 0; i < 4; i++) a[i] = As[kk][ty * 4 + i];
            #pragma unroll
            for (int j = 0; j < 4; j++) b[j] = Bs[kk][tx * 4 + j];
            #pragma unroll
            for (int i = 0; i < 4; i++)
                #pragma unroll
                for (int j = 0; j < 4; j++)
                    acc[i][j] += a[i] * b[j];
        }
        __syncthreads();
    }
    #pragma unroll
    for (int i = 0; i < 4; i++) {
        int r = row0 + ty * 4 + i;
        if (r >= M) continue;
        #pragma unroll
        for (int j = 0; j < 4; j++) {
            int c = col0 + tx * 4 + j;
            float v = acc[i][j];
            if (BIAS) v += bias[c];
            if (ACC) v += C[(size_t)r * Nn + c];
            C[(size_t)r * Nn + c] = v;
        }
    }
}

// ---------------- big GEMM (fc3): 128x128x8 tiles, 8x8 per thread -----------
__global__ void gemm_big(const float* __restrict__ A, const float* __restrict__ B,
                         const float* __restrict__ bias, float* __restrict__ C,
                         int M, int Nn, int K) {
    __shared__ float As[8][128];
    __shared__ float Bs[8][128];
    const int tid = threadIdx.x;
    const int ty = tid >> 4, tx = tid & 15;             // 16x16 threads
    const int row0 = blockIdx.y * 128, col0 = blockIdx.x * 128;
    const int arow = tid >> 1, ak = (tid & 1) * 4;      // A: 128 rows x 8 k
    const int bkr = tid >> 5, bcol = (tid & 31) * 4;    // B: 8 k x 128 cols
    float acc[8][8] = {};
    for (int k0 = 0; k0 < K; k0 += 8) {
        float4 av = make_float4(0.f, 0.f, 0.f, 0.f);
        if (row0 + arow < M)
            av = *(const float4*)(A + (size_t)(row0 + arow) * K + k0 + ak);
        As[ak + 0][arow] = av.x; As[ak + 1][arow] = av.y;
        As[ak + 2][arow] = av.z; As[ak + 3][arow] = av.w;
        float4 bv = make_float4(0.f, 0.f, 0.f, 0.f);
        if (col0 + bcol < Nn)
            bv = *(const float4*)(B + (size_t)(k0 + bkr) * Nn + col0 + bcol);
        *(float4*)(&Bs[bkr][bcol]) = bv;
        __syncthreads();
        #pragma unroll
        for (int kk = 0; kk < 8; kk++) {
            float4 a0 = *(const float4*)(&As[kk][ty * 4]);
            float4 a1 = *(const float4*)(&As[kk][64 + ty * 4]);
            float4 b0 = *(const float4*)(&Bs[kk][tx * 4]);
            float4 b1 = *(const float4*)(&Bs[kk][64 + tx * 4]);
            float a[8] = {a0.x, a0.y, a0.z, a0.w, a1.x, a1.y, a1.z, a1.w};
            float b[8] = {b0.x, b0.y, b0.z, b0.w, b1.x, b1.y, b1.z, b1.w};
            #pragma unroll
            for (int i = 0; i < 8; i++)
                #pragma unroll
                for (int j = 0; j < 8; j++)
                    acc[i][j] += a[i] * b[j];
        }
        __syncthreads();
    }
    #pragma unroll
    for (int i = 0; i < 8; i++) {
        int r = row0 + (i < 4 ? ty * 4 + i : 64 + ty * 4 + (i - 4));
        if (r >= M) continue;
        #pragma unroll
        for (int j = 0; j < 8; j++) {
            int c = col0 + (j < 4 ? tx * 4 + j : 64 + tx * 4 + (j - 4));
            if (c < Nn) C[(size_t)r * Nn + c] = acc[i][j] + bias[c];
        }
    }
}

// ---------------- Laplacian apply pieces ------------------------------------
__global__ void zero_dz() {
    g_dz[blockIdx.x * 256 + threadIdx.x] = 0.f;
}

// g_dz[64,64] += D[64,10000] @ Z[10000,64], split-K over 125 blocks of 80 rows
__global__ void dz_kernel(const float* __restrict__ Dm, const float* __restrict__ Z) {
    __shared__ float sD[4][64];
    __shared__ float sZ[4][64];
    const int tid = threadIdx.x;
    const int i4 = (tid >> 4) << 2;
    const int j4 = (tid & 15) << 2;
    float acc[4][4] = {};
    const int nb0 = blockIdx.x * 80;
    for (int nb = 0; nb < 80; nb += 4) {
        const int nbase = nb0 + nb;
        {
            int ii = tid >> 2, nn = tid & 3;
            sD[nn][ii] = Dm[(size_t)ii * N_V + nbase + nn];
            sZ[tid >> 6][tid & 63] = Z[(size_t)(nbase + (tid >> 6)) * 64 + (tid & 63)];
        }
        __syncthreads();
        #pragma unroll
        for (int nn = 0; nn < 4; nn++) {
            float d[4], z[4];
            #pragma unroll
            for (int a = 0; a < 4; a++) d[a] = sD[nn][i4 + a];
            #pragma unroll
            for (int b = 0; b < 4; b++) z[b] = sZ[nn][j4 + b];
            #pragma unroll
            for (int a = 0; a < 4; a++)
                #pragma unroll
                for (int b = 0; b < 4; b++)
                    acc[a][b] += d[a] * z[b];
        }
        __syncthreads();
    }
    #pragma unroll
    for (int a = 0; a < 4; a++)
        #pragma unroll
        for (int b = 0; b < 4; b++)
            atomicAdd(&g_dz[(i4 + a) * 64 + j4 + b], acc[a][b]);
}

// Y[10000,64] = V @ (eigs * g_dz);  mode=1: Y = 2*(V@M) - Tprev
__global__ void vdz_kernel(const float* __restrict__ V, const float* __restrict__ eigs,
                           const float* __restrict__ Tprev, float* __restrict__ Y,
                           int mode) {
    __shared__ float Ms[64][64];
    const int tid = threadIdx.x;
    for (int i = tid; i < 64 * 64; i += 256) {
        int k = i >> 6;
        Ms[k][i & 63] = eigs[k] * g_dz[i];
    }
    __syncthreads();
    const int row = blockIdx.x * 128 + (tid >> 1);
    if (row >= N_V) return;
    const int j0 = (tid & 1) * 32;
    float acc[32] = {};
    const float* vp = V + (size_t)row * 64;
    #pragma unroll 4
    for (int k = 0; k < 64; k++) {
        float a = vp[k];
        #pragma unroll
        for (int j = 0; j < 32; j++)
            acc[j] += a * Ms[k][j0 + j];
    }
    float* yp = Y + (size_t)row * 64 + j0;
    if (mode) {
        const float* tp = Tprev + (size_t)row * 64 + j0;
        #pragma unroll
        for (int j = 0; j < 32; j++) yp[j] = 2.f * acc[j] - tp[j];
    } else {
        #pragma unroll
        for (int j = 0; j < 32; j++) yp[j] = acc[j];
    }
}

// ---------------- BatchNorm (training-mode batch stats) ---------------------
__global__ void bn_stats(const float* __restrict__ X, const float* __restrict__ gam,
                         const float* __restrict__ bet, int C) {
    __shared__ float s1[256], s2v[256];
    const int c = blockIdx.x, tid = threadIdx.x;
    float s = 0.f, s2 = 0.f;
    for (int r = tid; r < N_V; r += 256) {
        float v = X[(size_t)r * C + c];
        s += v; s2 += v * v;
    }
    s1[tid] = s; s2v[tid] = s2;
    __syncthreads();
    for (int st = 128; st > 0; st >>= 1) {
        if (tid < st) { s1[tid] += s1[tid + st]; s2v[tid] += s2v[tid + st]; }
        __syncthreads();
    }
    if (tid == 0) {
        float mean = s1[0] * (1.f / N_V);
        float var = s2v[0] * (1.f / N_V) - mean * mean;
        float istd = rsqrtf(var + 1e-3f);
        float sc = gam[c] * istd;
        g_scale[c] = sc;
        g_shift[c] = bet[c] - mean * sc;
    }
}

__global__ void bn_apply(const float* __restrict__ X, float* __restrict__ Y,
                         int C, int total) {
    int i = blockIdx.x * 256 + threadIdx.x;
    if (i < total) {
        int c = i & (C - 1);   // C in {64,128,256}
        Y[i] = fmaxf(fmaf(X[i], g_scale[c], g_shift[c]), 0.f);
    }
}

// ---------------- in-place row log-softmax ----------------------------------
__global__ void lsm_kernel(float* __restrict__ out) {
    __shared__ float srow[N_V];     // 40 KB row cache
    __shared__ float red[256];
    const int row = blockIdx.x, tid = threadIdx.x;
    float* p = out + (size_t)row * N_V;
    float m = -1e30f;
    for (int i = tid; i < N_V; i += 256) {
        float v = p[i];
        srow[i] = v;
        m = fmaxf(m, v);
    }
    red[tid] = m;
    __syncthreads();
    for (int st = 128; st > 0; st >>= 1) {
        if (tid < st) red[tid] = fmaxf(red[tid], red[tid + st]);
        __syncthreads();
    }
    m = red[0];
    __syncthreads();
    float s = 0.f;
    for (int i = tid; i < N_V; i += 256) s += __expf(srow[i] - m);
    red[tid] = s;
    __syncthreads();
    for (int st = 128; st > 0; st >>= 1) {
        if (tid < st) red[tid] += red[tid + st];
        __syncthreads();
    }
    float lse = m + logf(red[0]);
    for (int i = tid; i < N_V; i += 256) p[i] = srow[i] - lse;
}

// ---------------- host orchestration ----------------------------------------
static void run_L(const float* Dm, const float* V, const float* eigs,
                  const float* Zin, const float* Tprev, float* Yout, int mode) {
    zero_dz<<<16, 256>>>();
    dz_kernel<<<125, 256>>>(Dm, Zin);
    vdz_kernel<<<(N_V + 127) / 128, 256>>>(V, eigs, Tprev, Yout, mode);
}

static void run_cheb(const float* X, const float* W, const float* cb,
                     const float* gam, const float* bet, int Cout,
                     const float* Dm, const float* V, const float* eigs,
                     float* acc, float* tA, float* tB, float* tC, float* Yout) {
    dim3 gs(Cout / 64, (N_V + 63) / 64);
    gemm_small<0, 1><<<gs, 256>>>(X, W, cb, acc, N_V, Cout, 64);
    run_L(Dm, V, eigs, X, nullptr, tA, 0);
    gemm_small<1, 0><<<gs, 256>>>(tA, W + (size_t)1 * 64 * Cout, nullptr, acc, N_V, Cout, 64);
    const float* prev = X;
    float* cur = tA;
    float* nxt[4] = {tB, tC, tA, tB};
    for (int k = 2; k < 6; k++) {
        float* nx = nxt[k - 2];
        run_L(Dm, V, eigs, cur, prev, nx, 1);
        gemm_small<1, 0><<<gs, 256>>>(nx, W + (size_t)k * 64 * Cout, nullptr, acc, N_V, Cout, 64);
        prev = cur; cur = nx;
    }
    bn_stats<<<Cout, 256>>>(acc, gam, bet, Cout);
    int total = N_V * Cout;
    bn_apply<<<(total + 255) / 256, 256>>>(acc, Yout, Cout, total);
}

extern "C" void kernel_launch(void* const* d_in, const int* in_sizes, int n_in,
                              void* d_out, int out_size) {
    const float* x     = (const float*)d_in[0];
    const float* V     = (const float*)d_in[1];
    const float* Dm    = (const float*)d_in[2];
    const float* eigs  = (const float*)d_in[3];
    const float* fc1_w = (const float*)d_in[4];
    const float* fc1_b = (const float*)d_in[5];
    const float* bf1_g = (const float*)d_in[6];
    const float* bf1_b = (const float*)d_in[7];
    const float* W1  = (const float*)d_in[8];
    const float* cb1 = (const float*)d_in[9];
    const float* b1g = (const float*)d_in[10];
    const float* b1b = (const float*)d_in[11];
    const float* W2  = (const float*)d_in[12];
    const float* cb2 = (const float*)d_in[13];
    const float* b2g = (const float*)d_in[14];
    const float* b2b = (const float*)d_in[15];
    const float* W3  = (const float*)d_in[16];
    const float* cb3 = (const float*)d_in[17];
    const float* b3g = (const float*)d_in[18];
    const float* b3b = (const float*)d_in[19];
    const float* fc2_w = (const float*)d_in[20];
    const float* fc2_b = (const float*)d_in[21];
    const float* bf2_g = (const float*)d_in[22];
    const float* bf2_b = (const float*)d_in[23];
    const float* fc3_w = (const float*)d_in[24];
    const float* fc3_b = (const float*)d_in[25];

    float* out  = (float*)d_out;
    float* desc = out + (size_t)N_V * N_V;   // outputs: [log_softmax | desc]

    float *acc, *h, *tA, *tB, *tC;
    cudaGetSymbolAddress((void**)&acc, g_acc);
    cudaGetSymbolAddress((void**)&h,   g_h);
    cudaGetSymbolAddress((void**)&tA,  g_tA);
    cudaGetSymbolAddress((void**)&tB,  g_tB);
    cudaGetSymbolAddress((void**)&tC,  g_tC);

    // fc1 + BN + relu -> h[10000,64]
    {
        dim3 g1(1, (N_V + 63) / 64);
        gemm_small<0, 1><<<g1, 256>>>(x, fc1_w, fc1_b, acc, N_V, 64, IN_DESC);
        bn_stats<<<64, 256>>>(acc, bf1_g, bf1_b, 64);
        int total = N_V * 64;
        bn_apply<<<(total + 255) / 256, 256>>>(acc, h, 64, total);
    }

    // three Chebyshev spectral-conv layers (+BN+relu), in place on h
    run_cheb(h, W1, cb1, b1g, b1b, 64,  Dm, V, eigs, acc, tA, tB, tC, h);
    run_cheb(h, W2, cb2, b2g, b2b, 64,  Dm, V, eigs, acc, tA, tB, tC, h);
    run_cheb(h, W3, cb3, b3g, b3b, 128, Dm, V, eigs, acc, tA, tB, tC, h);

    // fc2 + BN + relu -> desc (written straight into d_out tail)
    {
        dim3 g2(256 / 64, (N_V + 63) / 64);
        gemm_small<0, 1><<<g2, 256>>>(h, fc2_w, fc2_b, acc, N_V, 256, 128);
        bn_stats<<<256, 256>>>(acc, bf2_g, bf2_b, 256);
        int total = N_V * 256;
        bn_apply<<<(total + 255) / 256, 256>>>(acc, desc, 256, total);
    }

    // fc3: logits = desc @ fc3_w + fc3_b  -> d_out[0 : N*N]
    {
        dim3 g3((N_V + 127) / 128, (N_V + 127) / 128);
        gemm_big<<<g3, 256>>>(desc, fc3_w, fc3_b, out, N_V, N_V, 256);
    }

    // in-place row log-softmax
    lsm_kernel<<<N_V, 256>>>(out);
}

// round 4
// speedup vs baseline: 1.0033x; 1.0033x over previous
#include <cuda_runtime.h>
#include <math.h>

#define N_V 10000
#define NSPEC 64
#define IN_DESC 352
#define OUT_DESC 256

// ---------------- scratch (device globals; no allocations allowed) ----------
__device__ float g_acc[N_V * 256];   // pre-BN accumulator (max width 256: fc2)
__device__ float g_h[N_V * 128];     // current activations
__device__ float g_tA[N_V * 64];     // Chebyshev T buffers
__device__ float g_tB[N_V * 64];
__device__ float g_tC[N_V * 64];
__device__ float g_dz[NSPEC * NSPEC];
__device__ float g_scale[256];       // BN fused scale/shift
__device__ float g_shift[256];

// ---------------- small GEMM: C[M,N] = A[M,K] @ B[K,N] (+bias) (+=C) --------
// BM=BN=64, BK=16, 256 threads, 4x4 per thread. K%16==0, N%64==0 assumed.
template<int ACC, int BIAS>
__global__ void gemm_small(const float* __restrict__ A, const float* __restrict__ B,
                           const float* __restrict__ bias, float* __restrict__ C,
                           int M, int Nn, int K) {
    __shared__ float As[16][64];
    __shared__ float Bs[16][64];
    const int tid = threadIdx.x;
    const int ty = tid >> 4, tx = tid & 15;
    const int row0 = blockIdx.y * 64, col0 = blockIdx.x * 64;
    const int arow = tid >> 2, ak = (tid & 3) << 2;
    const int bk = tid >> 4, bcol = (tid & 15) << 2;
    float acc[4][4] = {};
    for (int k0 = 0; k0 < K; k0 += 16) {
        float4 av = make_float4(0.f, 0.f, 0.f, 0.f);
        if (row0 + arow < M)
            av = *(const float4*)(A + (size_t)(row0 + arow) * K + k0 + ak);
        As[ak + 0][arow] = av.x; As[ak + 1][arow] = av.y;
        As[ak + 2][arow] = av.z; As[ak + 3][arow] = av.w;
        float4 bv = *(const float4*)(B + (size_t)(k0 + bk) * Nn + col0 + bcol);
        *(float4*)(&Bs[bk][bcol]) = bv;
        __syncthreads();
        #pragma unroll
        for (int kk = 0; kk < 16; kk++) {
            float a[4], b[4];
            #pragma unroll
            for (int i = 0; i < 4; i++) a[i] = As[kk][ty * 4 + i];
            #pragma unroll
            for (int j = 0; j < 4; j++) b[j] = Bs[kk][tx * 4 + j];
            #pragma unroll
            for (int i = 0; i < 4; i++)
                #pragma unroll
                for (int j = 0; j < 4; j++)
                    acc[i][j] += a[i] * b[j];
        }
        __syncthreads();
    }
    #pragma unroll
    for (int i = 0; i < 4; i++) {
        int r = row0 + ty * 4 + i;
        if (r >= M) continue;
        #pragma unroll
        for (int j = 0; j < 4; j++) {
            int c = col0 + tx * 4 + j;
            float v = acc[i][j];
            if (BIAS) v += bias[c];
            if (ACC) v += C[(size_t)r * Nn + c];
            C[(size_t)r * Nn + c] = v;
        }
    }
}

// ---------------- big GEMM (fc3): 128x128x8 tiles, 8x8 per thread -----------
__global__ void gemm_big(const float* __restrict__ A, const float* __restrict__ B,
                         const float* __restrict__ bias, float* __restrict__ C,
                         int M, int Nn, int K) {
    __shared__ float As[8][128];
    __shared__ float Bs[8][128];
    const int tid = threadIdx.x;
    const int ty = tid >> 4, tx = tid & 15;             // 16x16 threads
    const int row0 = blockIdx.y * 128, col0 = blockIdx.x * 128;
    const int arow = tid >> 1, ak = (tid & 1) * 4;      // A: 128 rows x 8 k
    const int bkr = tid >> 5, bcol = (tid & 31) * 4;    // B: 8 k x 128 cols
    float acc[8][8] = {};
    for (int k0 = 0; k0 < K; k0 += 8) {
        float4 av = make_float4(0.f, 0.f, 0.f, 0.f);
        if (row0 + arow < M)
            av = *(const float4*)(A + (size_t)(row0 + arow) * K + k0 + ak);
        As[ak + 0][arow] = av.x; As[ak + 1][arow] = av.y;
        As[ak + 2][arow] = av.z; As[ak + 3][arow] = av.w;
        float4 bv = make_float4(0.f, 0.f, 0.f, 0.f);
        if (col0 + bcol < Nn)
            bv = *(const float4*)(B + (size_t)(k0 + bkr) * Nn + col0 + bcol);
        *(float4*)(&Bs[bkr][bcol]) = bv;
        __syncthreads();
        #pragma unroll
        for (int kk = 0; kk < 8; kk++) {
            float4 a0 = *(const float4*)(&As[kk][ty * 4]);
            float4 a1 = *(const float4*)(&As[kk][64 + ty * 4]);
            float4 b0 = *(const float4*)(&Bs[kk][tx * 4]);
            float4 b1 = *(const float4*)(&Bs[kk][64 + tx * 4]);
            float a[8] = {a0.x, a0.y, a0.z, a0.w, a1.x, a1.y, a1.z, a1.w};
            float b[8] = {b0.x, b0.y, b0.z, b0.w, b1.x, b1.y, b1.z, b1.w};
            #pragma unroll
            for (int i = 0; i < 8; i++)
                #pragma unroll
                for (int j = 0; j < 8; j++)
                    acc[i][j] += a[i] * b[j];
        }
        __syncthreads();
    }
    #pragma unroll
    for (int i = 0; i < 8; i++) {
        int r = row0 + (i < 4 ? ty * 4 + i : 64 + ty * 4 + (i - 4));
        if (r >= M) continue;
        #pragma unroll
        for (int j = 0; j < 8; j++) {
            int c = col0 + (j < 4 ? tx * 4 + j : 64 + tx * 4 + (j - 4));
            if (c < Nn) C[(size_t)r * Nn + c] = acc[i][j] + bias[c];
        }
    }
}

// ---------------- Laplacian apply pieces ------------------------------------
__global__ void zero_dz() {
    g_dz[blockIdx.x * 256 + threadIdx.x] = 0.f;
}

// g_dz[64,64] += D[64,10000] @ Z[10000,64], split-K over 125 blocks of 80 rows
__global__ void dz_kernel(const float* __restrict__ Dm, const float* __restrict__ Z) {
    __shared__ float sD[4][64];
    __shared__ float sZ[4][64];
    const int tid = threadIdx.x;
    const int i4 = (tid >> 4) << 2;
    const int j4 = (tid & 15) << 2;
    float acc[4][4] = {};
    const int nb0 = blockIdx.x * 80;
    for (int nb = 0; nb < 80; nb += 4) {
        const int nbase = nb0 + nb;
        {
            int ii = tid >> 2, nn = tid & 3;
            sD[nn][ii] = Dm[(size_t)ii * N_V + nbase + nn];
            sZ[tid >> 6][tid & 63] = Z[(size_t)(nbase + (tid >> 6)) * 64 + (tid & 63)];
        }
        __syncthreads();
        #pragma unroll
        for (int nn = 0; nn < 4; nn++) {
            float d[4], z[4];
            #pragma unroll
            for (int a = 0; a < 4; a++) d[a] = sD[nn][i4 + a];
            #pragma unroll
            for (int b = 0; b < 4; b++) z[b] = sZ[nn][j4 + b];
            #pragma unroll
            for (int a = 0; a < 4; a++)
                #pragma unroll
                for (int b = 0; b < 4; b++)
                    acc[a][b] += d[a] * z[b];
        }
        __syncthreads();
    }
    #pragma unroll
    for (int a = 0; a < 4; a++)
        #pragma unroll
        for (int b = 0; b < 4; b++)
            atomicAdd(&g_dz[(i4 + a) * 64 + j4 + b], acc[a][b]);
}

// Y[10000,64] = V @ (eigs * g_dz);  mode=1: Y = 2*(V@M) - Tprev
__global__ void vdz_kernel(const float* __restrict__ V, const float* __restrict__ eigs,
                           const float* __restrict__ Tprev, float* __restrict__ Y,
                           int mode) {
    __shared__ float Ms[64][64];
    const int tid = threadIdx.x;
    for (int i = tid; i < 64 * 64; i += 256) {
        int k = i >> 6;
        Ms[k][i & 63] = eigs[k] * g_dz[i];
    }
    __syncthreads();
    const int row = blockIdx.x * 128 + (tid >> 1);
    if (row >= N_V) return;
    const int j0 = (tid & 1) * 32;
    float acc[32] = {};
    const float* vp = V + (size_t)row * 64;
    #pragma unroll 4
    for (int k = 0; k < 64; k++) {
        float a = vp[k];
        #pragma unroll
        for (int j = 0; j < 32; j++)
            acc[j] += a * Ms[k][j0 + j];
    }
    float* yp = Y + (size_t)row * 64 + j0;
    if (mode) {
        const float* tp = Tprev + (size_t)row * 64 + j0;
        #pragma unroll
        for (int j = 0; j < 32; j++) yp[j] = 2.f * acc[j] - tp[j];
    } else {
        #pragma unroll
        for (int j = 0; j < 32; j++) yp[j] = acc[j];
    }
}

// ---------------- BatchNorm (training-mode batch stats) ---------------------
__global__ void bn_stats(const float* __restrict__ X, const float* __restrict__ gam,
                         const float* __restrict__ bet, int C) {
    __shared__ float s1[256], s2v[256];
    const int c = blockIdx.x, tid = threadIdx.x;
    float s = 0.f, s2 = 0.f;
    for (int r = tid; r < N_V; r += 256) {
        float v = X[(size_t)r * C + c];
        s += v; s2 += v * v;
    }
    s1[tid] = s; s2v[tid] = s2;
    __syncthreads();
    for (int st = 128; st > 0; st >>= 1) {
        if (tid < st) { s1[tid] += s1[tid + st]; s2v[tid] += s2v[tid + st]; }
        __syncthreads();
    }
    if (tid == 0) {
        float mean = s1[0] * (1.f / N_V);
        float var = s2v[0] * (1.f / N_V) - mean * mean;
        float istd = rsqrtf(var + 1e-3f);
        float sc = gam[c] * istd;
        g_scale[c] = sc;
        g_shift[c] = bet[c] - mean * sc;
    }
}

__global__ void bn_apply(const float* __restrict__ X, float* __restrict__ Y,
                         int C, int total) {
    int i = blockIdx.x * 256 + threadIdx.x;
    if (i < total) {
        int c = i & (C - 1);   // C in {64,128,256}
        Y[i] = fmaxf(fmaf(X[i], g_scale[c], g_shift[c]), 0.f);
    }
}

// ---------------- in-place row log-softmax ----------------------------------
__global__ void lsm_kernel(float* __restrict__ out) {
    __shared__ float srow[N_V];     // 40 KB row cache
    __shared__ float red[256];
    const int row = blockIdx.x, tid = threadIdx.x;
    float* p = out + (size_t)row * N_V;
    float m = -1e30f;
    for (int i = tid; i < N_V; i += 256) {
        float v = p[i];
        srow[i] = v;
        m = fmaxf(m, v);
    }
    red[tid] = m;
    __syncthreads();
    for (int st = 128; st > 0; st >>= 1) {
        if (tid < st) red[tid] = fmaxf(red[tid], red[tid + st]);
        __syncthreads();
    }
    m = red[0];
    __syncthreads();
    float s = 0.f;
    for (int i = tid; i < N_V; i += 256) s += __expf(srow[i] - m);
    red[tid] = s;
    __syncthreads();
    for (int st = 128; st > 0; st >>= 1) {
        if (tid < st) red[tid] += red[tid + st];
        __syncthreads();
    }
    float lse = m + logf(red[0]);
    for (int i = tid; i < N_V; i += 256) p[i] = srow[i] - lse;
}

// ---------------- host orchestration ----------------------------------------
static void run_L(const float* Dm, const float* V, const float* eigs,
                  const float* Zin, const float* Tprev, float* Yout, int mode) {
    zero_dz<<<16, 256>>>();
    dz_kernel<<<125, 256>>>(Dm, Zin);
    vdz_kernel<<<(N_V + 127) / 128, 256>>>(V, eigs, Tprev, Yout, mode);
}

static void run_cheb(const float* X, const float* W, const float* cb,
                     const float* gam, const float* bet, int Cout,
                     const float* Dm, const float* V, const float* eigs,
                     float* acc, float* tA, float* tB, float* tC, float* Yout) {
    dim3 gs(Cout / 64, (N_V + 63) / 64);
    gemm_small<0, 1><<<gs, 256>>>(X, W, cb, acc, N_V, Cout, 64);
    run_L(Dm, V, eigs, X, nullptr, tA, 0);
    gemm_small<1, 0><<<gs, 256>>>(tA, W + (size_t)1 * 64 * Cout, nullptr, acc, N_V, Cout, 64);
    const float* prev = X;
    float* cur = tA;
    float* nxt[4] = {tB, tC, tA, tB};
    for (int k = 2; k < 6; k++) {
        float* nx = nxt[k - 2];
        run_L(Dm, V, eigs, cur, prev, nx, 1);
        gemm_small<1, 0><<<gs, 256>>>(nx, W + (size_t)k * 64 * Cout, nullptr, acc, N_V, Cout, 64);
        prev = cur; cur = nx;
    }
    bn_stats<<<Cout, 256>>>(acc, gam, bet, Cout);
    int total = N_V * Cout;
    bn_apply<<<(total + 255) / 256, 256>>>(acc, Yout, Cout, total);
}

extern "C" void kernel_launch(void* const* d_in, const int* in_sizes, int n_in,
                              void* d_out, int out_size) {
    const float* x     = (const float*)d_in[0];
    const float* V     = (const float*)d_in[1];
    const float* Dm    = (const float*)d_in[2];
    const float* eigs  = (const float*)d_in[3];
    const float* fc1_w = (const float*)d_in[4];
    const float* fc1_b = (const float*)d_in[5];
    const float* bf1_g = (const float*)d_in[6];
    const float* bf1_b = (const float*)d_in[7];
    const float* W1  = (const float*)d_in[8];
    const float* cb1 = (const float*)d_in[9];
    const float* b1g = (const float*)d_in[10];
    const float* b1b = (const float*)d_in[11];
    const float* W2  = (const float*)d_in[12];
    const float* cb2 = (const float*)d_in[13];
    const float* b2g = (const float*)d_in[14];
    const float* b2b = (const float*)d_in[15];
    const float* W3  = (const float*)d_in[16];
    const float* cb3 = (const float*)d_in[17];
    const float* b3g = (const float*)d_in[18];
    const float* b3b = (const float*)d_in[19];
    const float* fc2_w = (const float*)d_in[20];
    const float* fc2_b = (const float*)d_in[21];
    const float* bf2_g = (const float*)d_in[22];
    const float* bf2_b = (const float*)d_in[23];
    const float* fc3_w = (const float*)d_in[24];
    const float* fc3_b = (const float*)d_in[25];

    float* out  = (float*)d_out;
    float* desc = out + (size_t)N_V * N_V;   // outputs: [log_softmax | desc]

    float *acc, *h, *tA, *tB, *tC;
    cudaGetSymbolAddress((void**)&acc, g_acc);
    cudaGetSymbolAddress((void**)&h,   g_h);
    cudaGetSymbolAddress((void**)&tA,  g_tA);
    cudaGetSymbolAddress((void**)&tB,  g_tB);
    cudaGetSymbolAddress((void**)&tC,  g_tC);

    // fc1 + BN + relu -> h[10000,64]
    {
        dim3 g1(1, (N_V + 63) / 64);
        gemm_small<0, 1><<<g1, 256>>>(x, fc1_w, fc1_b, acc, N_V, 64, IN_DESC);
        bn_stats<<<64, 256>>>(acc, bf1_g, bf1_b, 64);
        int total = N_V * 64;
        bn_apply<<<(total + 255) / 256, 256>>>(acc, h, 64, total);
    }

    // three Chebyshev spectral-conv layers (+BN+relu), in place on h
    run_cheb(h, W1, cb1, b1g, b1b, 64,  Dm, V, eigs, acc, tA, tB, tC, h);
    run_cheb(h, W2, cb2, b2g, b2b, 64,  Dm, V, eigs, acc, tA, tB, tC, h);
    run_cheb(h, W3, cb3, b3g, b3b, 128, Dm, V, eigs, acc, tA, tB, tC, h);

    // fc2 + BN + relu -> desc (written straight into d_out tail)
    {
        dim3 g2(256 / 64, (N_V + 63) / 64);
        gemm_small<0, 1><<<g2, 256>>>(h, fc2_w, fc2_b, acc, N_V, 256, 128);
        bn_stats<<<256, 256>>>(acc, bf2_g, bf2_b, 256);
        int total = N_V * 256;
        bn_apply<<<(total + 255) / 256, 256>>>(acc, desc, 256, total);
    }

    // fc3: logits = desc @ fc3_w + fc3_b  -> d_out[0 : N*N]
    {
        dim3 g3((N_V + 127) / 128, (N_V + 127) / 128);
        gemm_big<<<g3, 256>>>(desc, fc3_w, fc3_b, out, N_V, N_V, 256);
    }

    // in-place row log-softmax
    lsm_kernel<<<N_V, 256>>>(out);
}

// round 6
// speedup vs baseline: 1.3699x; 1.3654x over previous
#include <cuda_runtime.h>
#include <cuda_bf16.h>
#include <math.h>
#include <stdint.h>

#define N_V 10000
#define NSPEC 64
#define IN_DESC 352
#define OUT_DESC 256

// ---------------- scratch (device globals; no allocations allowed) ----------
__device__ float g_acc[N_V * 256];   // pre-BN accumulator (max width 256: fc2)
__device__ float g_h[N_V * 128];     // current activations
__device__ float g_tA[N_V * 64];     // Chebyshev T buffers
__device__ float g_tB[N_V * 64];
__device__ float g_tC[N_V * 64];
__device__ float g_dz[NSPEC * NSPEC];
__device__ float g_scale[256];       // BN fused scale/shift
__device__ float g_shift[256];
__device__ __nv_bfloat16 g_bh[N_V * 256];  // fc3_w transposed [N,K], hi split
__device__ __nv_bfloat16 g_bl[N_V * 256];  // lo split
__device__ __nv_bfloat16 g_ah[N_V * 256];  // desc [M,K], hi split
__device__ __nv_bfloat16 g_al[N_V * 256];  // lo split

// ---------------- mma.sync helpers (base sm_103-legal, no 'a' features) -----
__device__ __forceinline__ uint32_t smem_u32(const void* p) {
    uint32_t a;
    asm("{ .reg .u64 t; cvta.to.shared.u64 t, %1; cvt.u32.u64 %0, t; }" : "=r"(a) : "l"(p));
    return a;
}
#define LDSM_X4(r0, r1, r2, r3, addr) \
    asm volatile("ldmatrix.sync.aligned.m8n8.x4.shared.b16 {%0,%1,%2,%3}, [%4];" \
        : "=r"(r0), "=r"(r1), "=r"(r2), "=r"(r3) : "r"(addr))
#define LDSM_X2(r0, r1, addr) \
    asm volatile("ldmatrix.sync.aligned.m8n8.x2.shared.b16 {%0,%1}, [%2];" \
        : "=r"(r0), "=r"(r1) : "r"(addr))
#define MMA_BF16(c, a, b) \
    asm volatile("mma.sync.aligned.m16n8k16.row.col.f32.bf16.bf16.f32 " \
        "{%0,%1,%2,%3}, {%4,%5,%6,%7}, {%8,%9}, {%0,%1,%2,%3};" \
        : "+f"((c)[0]), "+f"((c)[1]), "+f"((c)[2]), "+f"((c)[3]) \
        : "r"((a)[0]), "r"((a)[1]), "r"((a)[2]), "r"((a)[3]), "r"((b)[0]), "r"((b)[1]))

__device__ __forceinline__ uint32_t sw128(uint32_t off) {
    return off ^ ((off >> 3) & 0x70);
}
__device__ __forceinline__ uint32_t packb(__nv_bfloat16 a, __nv_bfloat16 b) {
    unsigned short ua = *reinterpret_cast<unsigned short*>(&a);
    unsigned short ub = *reinterpret_cast<unsigned short*>(&b);
    return (uint32_t)ua | ((uint32_t)ub << 16);
}

// ---------------- fc3_w pre-transpose + bf16 split: [K=256,N] -> [N,K] ------
__global__ void split_b_kernel(const float* __restrict__ W) {
    __shared__ float s[32][33];
    const int tx = threadIdx.x, ty = threadIdx.y;
    const int n0 = blockIdx.x * 32, k0 = blockIdx.y * 32;
    float v = 0.f;
    if (n0 + tx < N_V) v = W[(size_t)(k0 + ty) * N_V + n0 + tx];
    s[ty][tx] = v;
    __syncthreads();
    int n = n0 + ty;
    if (n < N_V) {
        float x = s[tx][ty];
        __nv_bfloat16 hb = __float2bfloat16(x);
        float r = x - __bfloat162float(hb);
        g_bh[(size_t)n * 256 + k0 + tx] = hb;
        g_bl[(size_t)n * 256 + k0 + tx] = __float2bfloat16(r);
    }
}

// ---------------- desc bf16 split: [M,K] fp32 -> hi/lo bf16 ------------------
__global__ void split_a_kernel(const float* __restrict__ A) {
    int i = blockIdx.x * 256 + threadIdx.x;       // over N_V*64 float4 chunks
    if (i < N_V * 64) {
        float4 f = ((const float4*)A)[i];
        __nv_bfloat16 h0 = __float2bfloat16(f.x), h1 = __float2bfloat16(f.y);
        __nv_bfloat16 h2 = __float2bfloat16(f.z), h3 = __float2bfloat16(f.w);
        uint2 hv, lv;
        hv.x = packb(h0, h1); hv.y = packb(h2, h3);
        lv.x = packb(__float2bfloat16(f.x - __bfloat162float(h0)),
                     __float2bfloat16(f.y - __bfloat162float(h1)));
        lv.y = packb(__float2bfloat16(f.z - __bfloat162float(h2)),
                     __float2bfloat16(f.w - __bfloat162float(h3)));
        ((uint2*)g_ah)[i] = hv;
        ((uint2*)g_al)[i] = lv;
    }
}

// ---------------- fc3 GEMM via mma.sync bf16x3 -------------------------------
// C[10000,10000] = A[10000,256] @ B[N,K]^T + bias
// CTA: 128x128 tile, 256 threads = 8 warps (2m x 4n), warp tile 64x32.
// K chunked by 64 through SW128-swizzled SMEM. D = Ah*Bh + Ah*Bl + Al*Bh.
#define SM_AH 0
#define SM_AL 16384
#define SM_BH 32768
#define SM_BL 49152
#define SM_TOT 65536

__global__ __launch_bounds__(256, 1)
void fc3_kernel(const float* __restrict__ bias, float* __restrict__ C) {
    extern __shared__ char smem[];
    const uint32_t sbase = smem_u32(smem);
    const int tid = threadIdx.x;
    const int wid = tid >> 5, lane = tid & 31;
    const int wm = wid >> 2, wn = wid & 3;        // warp grid 2 x 4
    const int row0 = blockIdx.y * 128, col0 = blockIdx.x * 128;

    float acc[4][4][4] = {};                       // [mt][nt][frag]

    // ldmatrix per-lane address components
    const int l15 = lane & 15;
    const uint32_t a_row = (uint32_t)(wm * 64 + l15);       // + mt*16
    const uint32_t a_halfb = (uint32_t)((lane >> 4) * 16);  // k-half within 16
    const uint32_t b_row = (uint32_t)(wn * 32 + (l15 & 7)); // + nt*8
    const uint32_t b_halfb = (uint32_t)((l15 >> 3) * 16);

    for (int kc = 0; kc < 4; kc++) {
        __syncthreads();
        // ---- load 4 chunk buffers: 128 rows x 64 bf16 (128B/row), swizzled --
        const uint4 zero4 = make_uint4(0, 0, 0, 0);
        #pragma unroll
        for (int t = 0; t < 4; t++) {
            int i = tid + t * 256;                 // 0..1023
            int r = i >> 3, c = i & 7;             // row, 16B chunk
            uint32_t soff = sw128((uint32_t)(r * 128 + c * 16));
            size_t gb = (size_t)(row0 + r) * 512 + (size_t)kc * 128 + c * 16;
            uint4 vah = zero4, val = zero4;
            if (row0 + r < N_V) {
                vah = *(const uint4*)((const char*)g_ah + gb);
                val = *(const uint4*)((const char*)g_al + gb);
            }
            *(uint4*)(smem + SM_AH + soff) = vah;
            *(uint4*)(smem + SM_AL + soff) = val;
            size_t hb = (size_t)(col0 + r) * 512 + (size_t)kc * 128 + c * 16;
            uint4 vbh = zero4, vbl = zero4;
            if (col0 + r < N_V) {
                vbh = *(const uint4*)((const char*)g_bh + hb);
                vbl = *(const uint4*)((const char*)g_bl + hb);
            }
            *(uint4*)(smem + SM_BH + soff) = vbh;
            *(uint4*)(smem + SM_BL + soff) = vbl;
        }
        __syncthreads();

        // ---- 4 k16-steps of mma ----
        #pragma unroll
        for (int ks = 0; ks < 4; ks++) {
            uint32_t ah[4][4], al[4][4], bh[4][2], bl[4][2];
            #pragma unroll
            for (int mt = 0; mt < 4; mt++) {
                uint32_t off = sw128((a_row + mt * 16) * 128 + ks * 32 + a_halfb);
                LDSM_X4(ah[mt][0], ah[mt][1], ah[mt][2], ah[mt][3], sbase + SM_AH + off);
                LDSM_X4(al[mt][0], al[mt][1], al[mt][2], al[mt][3], sbase + SM_AL + off);
            }
            #pragma unroll
            for (int nt = 0; nt < 4; nt++) {
                uint32_t off = sw128((b_row + nt * 8) * 128 + ks * 32 + b_halfb);
                LDSM_X2(bh[nt][0], bh[nt][1], sbase + SM_BH + off);
                LDSM_X2(bl[nt][0], bl[nt][1], sbase + SM_BL + off);
            }
            #pragma unroll
            for (int mt = 0; mt < 4; mt++)
                #pragma unroll
                for (int nt = 0; nt < 4; nt++) {
                    MMA_BF16(acc[mt][nt], ah[mt], bh[nt]);
                    MMA_BF16(acc[mt][nt], ah[mt], bl[nt]);
                    MMA_BF16(acc[mt][nt], al[mt], bh[nt]);
                }
        }
    }

    // ---- epilogue: direct float2 stores + bias ----
    const int r_base = row0 + wm * 64 + (lane >> 2);
    const int c_base = col0 + wn * 32 + ((lane & 3) << 1);
    #pragma unroll
    for (int mt = 0; mt < 4; mt++) {
        #pragma unroll
        for (int nt = 0; nt < 4; nt++) {
            int cc = c_base + nt * 8;
            if (cc >= N_V) continue;
            float2 bb = *(const float2*)(bias + cc);
            int rr = r_base + mt * 16;
            if (rr < N_V) {
                float2 v = make_float2(acc[mt][nt][0] + bb.x, acc[mt][nt][1] + bb.y);
                *(float2*)(C + (size_t)rr * N_V + cc) = v;
            }
            if (rr + 8 < N_V) {
                float2 v = make_float2(acc[mt][nt][2] + bb.x, acc[mt][nt][3] + bb.y);
                *(float2*)(C + (size_t)(rr + 8) * N_V + cc) = v;
            }
        }
    }
}

// ---------------- small GEMM: C[M,N] = A[M,K] @ B[K,N] (+bias) (+=C) --------
template<int ACC, int BIAS>
__global__ void gemm_small(const float* __restrict__ A, const float* __restrict__ B,
                           const float* __restrict__ bias, float* __restrict__ C,
                           int M, int Nn, int K) {
    __shared__ float As[16][64];
    __shared__ float Bs[16][64];
    const int tid = threadIdx.x;
    const int ty = tid >> 4, tx = tid & 15;
    const int row0 = blockIdx.y * 64, col0 = blockIdx.x * 64;
    const int arow = tid >> 2, ak = (tid & 3) << 2;
    const int bk = tid >> 4, bcol = (tid & 15) << 2;
    float acc[4][4] = {};
    for (int k0 = 0; k0 < K; k0 += 16) {
        float4 av = make_float4(0.f, 0.f, 0.f, 0.f);
        if (row0 + arow < M)
            av = *(const float4*)(A + (size_t)(row0 + arow) * K + k0 + ak);
        As[ak + 0][arow] = av.x; As[ak + 1][arow] = av.y;
        As[ak + 2][arow] = av.z; As[ak + 3][arow] = av.w;
        float4 bv = *(const float4*)(B + (size_t)(k0 + bk) * Nn + col0 + bcol);
        *(float4*)(&Bs[bk][bcol]) = bv;
        __syncthreads();
        #pragma unroll
        for (int kk = 0; kk < 16; kk++) {
            float a[4], b[4];
            #pragma unroll
            for (int i = 0; i < 4; i++) a[i] = As[kk][ty * 4 + i];
            #pragma unroll
            for (int j = 0; j < 4; j++) b[j] = Bs[kk][tx * 4 + j];
            #pragma unroll
            for (int i = 0; i < 4; i++)
                #pragma unroll
                for (int j = 0; j < 4; j++)
                    acc[i][j] += a[i] * b[j];
        }
        __syncthreads();
    }
    #pragma unroll
    for (int i = 0; i < 4; i++) {
        int r = row0 + ty * 4 + i;
        if (r >= M) continue;
        #pragma unroll
        for (int j = 0; j < 4; j++) {
            int c = col0 + tx * 4 + j;
            float v = acc[i][j];
            if (BIAS) v += bias[c];
            if (ACC) v += C[(size_t)r * Nn + c];
            C[(size_t)r * Nn + c] = v;
        }
    }
}

// ---------------- Laplacian apply pieces ------------------------------------
__global__ void zero_dz() {
    g_dz[blockIdx.x * 256 + threadIdx.x] = 0.f;
}

__global__ void dz_kernel(const float* __restrict__ Dm, const float* __restrict__ Z) {
    __shared__ float sD[4][64];
    __shared__ float sZ[4][64];
    const int tid = threadIdx.x;
    const int i4 = (tid >> 4) << 2;
    const int j4 = (tid & 15) << 2;
    float acc[4][4] = {};
    const int nb0 = blockIdx.x * 80;
    for (int nb = 0; nb < 80; nb += 4) {
        const int nbase = nb0 + nb;
        {
            int ii = tid >> 2, nn = tid & 3;
            sD[nn][ii] = Dm[(size_t)ii * N_V + nbase + nn];
            sZ[tid >> 6][tid & 63] = Z[(size_t)(nbase + (tid >> 6)) * 64 + (tid & 63)];
        }
        __syncthreads();
        #pragma unroll
        for (int nn = 0; nn < 4; nn++) {
            float d[4], z[4];
            #pragma unroll
            for (int a = 0; a < 4; a++) d[a] = sD[nn][i4 + a];
            #pragma unroll
            for (int b = 0; b < 4; b++) z[b] = sZ[nn][j4 + b];
            #pragma unroll
            for (int a = 0; a < 4; a++)
                #pragma unroll
                for (int b = 0; b < 4; b++)
                    acc[a][b] += d[a] * z[b];
        }
        __syncthreads();
    }
    #pragma unroll
    for (int a = 0; a < 4; a++)
        #pragma unroll
        for (int b = 0; b < 4; b++)
            atomicAdd(&g_dz[(i4 + a) * 64 + j4 + b], acc[a][b]);
}

__global__ void vdz_kernel(const float* __restrict__ V, const float* __restrict__ eigs,
                           const float* __restrict__ Tprev, float* __restrict__ Y,
                           int mode) {
    __shared__ float Ms[64][64];
    const int tid = threadIdx.x;
    for (int i = tid; i < 64 * 64; i += 256) {
        int k = i >> 6;
        Ms[k][i & 63] = eigs[k] * g_dz[i];
    }
    __syncthreads();
    const int row = blockIdx.x * 128 + (tid >> 1);
    if (row >= N_V) return;
    const int j0 = (tid & 1) * 32;
    float acc[32] = {};
    const float* vp = V + (size_t)row * 64;
    #pragma unroll 4
    for (int k = 0; k < 64; k++) {
        float a = vp[k];
        #pragma unroll
        for (int j = 0; j < 32; j++)
            acc[j] += a * Ms[k][j0 + j];
    }
    float* yp = Y + (size_t)row * 64 + j0;
    if (mode) {
        const float* tp = Tprev + (size_t)row * 64 + j0;
        #pragma unroll
        for (int j = 0; j < 32; j++) yp[j] = 2.f * acc[j] - tp[j];
    } else {
        #pragma unroll
        for (int j = 0; j < 32; j++) yp[j] = acc[j];
    }
}

// ---------------- BatchNorm (training-mode batch stats) ---------------------
__global__ void bn_stats(const float* __restrict__ X, const float* __restrict__ gam,
                         const float* __restrict__ bet, int C) {
    __shared__ float s1[256], s2v[256];
    const int c = blockIdx.x, tid = threadIdx.x;
    float s = 0.f, s2 = 0.f;
    for (int r = tid; r < N_V; r += 256) {
        float v = X[(size_t)r * C + c];
        s += v; s2 += v * v;
    }
    s1[tid] = s; s2v[tid] = s2;
    __syncthreads();
    for (int st = 128; st > 0; st >>= 1) {
        if (tid < st) { s1[tid] += s1[tid + st]; s2v[tid] += s2v[tid + st]; }
        __syncthreads();
    }
    if (tid == 0) {
        float mean = s1[0] * (1.f / N_V);
        float var = s2v[0] * (1.f / N_V) - mean * mean;
        float istd = rsqrtf(var + 1e-3f);
        float sc = gam[c] * istd;
        g_scale[c] = sc;
        g_shift[c] = bet[c] - mean * sc;
    }
}

__global__ void bn_apply(const float* __restrict__ X, float* __restrict__ Y,
                         int C, int total) {
    int i = blockIdx.x * 256 + threadIdx.x;
    if (i < total) {
        int c = i & (C - 1);
        Y[i] = fmaxf(fmaf(X[i], g_scale[c], g_shift[c]), 0.f);
    }
}

// ---------------- in-place row log-softmax ----------------------------------
__global__ void lsm_kernel(float* __restrict__ out) {
    __shared__ float srow[N_V];
    __shared__ float red[256];
    const int row = blockIdx.x, tid = threadIdx.x;
    float* p = out + (size_t)row * N_V;
    float m = -1e30f;
    for (int i = tid; i < N_V; i += 256) {
        float v = p[i];
        srow[i] = v;
        m = fmaxf(m, v);
    }
    red[tid] = m;
    __syncthreads();
    for (int st = 128; st > 0; st >>= 1) {
        if (tid < st) red[tid] = fmaxf(red[tid], red[tid + st]);
        __syncthreads();
    }
    m = red[0];
    __syncthreads();
    float s = 0.f;
    for (int i = tid; i < N_V; i += 256) s += __expf(srow[i] - m);
    red[tid] = s;
    __syncthreads();
    for (int st = 128; st > 0; st >>= 1) {
        if (tid < st) red[tid] += red[tid + st];
        __syncthreads();
    }
    float lse = m + logf(red[0]);
    for (int i = tid; i < N_V; i += 256) p[i] = srow[i] - lse;
}

// ---------------- host orchestration ----------------------------------------
static void run_L(const float* Dm, const float* V, const float* eigs,
                  const float* Zin, const float* Tprev, float* Yout, int mode) {
    zero_dz<<<16, 256>>>();
    dz_kernel<<<125, 256>>>(Dm, Zin);
    vdz_kernel<<<(N_V + 127) / 128, 256>>>(V, eigs, Tprev, Yout, mode);
}

static void run_cheb(const float* X, const float* W, const float* cb,
                     const float* gam, const float* bet, int Cout,
                     const float* Dm, const float* V, const float* eigs,
                     float* acc, float* tA, float* tB, float* tC, float* Yout) {
    dim3 gs(Cout / 64, (N_V + 63) / 64);
    gemm_small<0, 1><<<gs, 256>>>(X, W, cb, acc, N_V, Cout, 64);
    run_L(Dm, V, eigs, X, nullptr, tA, 0);
    gemm_small<1, 0><<<gs, 256>>>(tA, W + (size_t)1 * 64 * Cout, nullptr, acc, N_V, Cout, 64);
    const float* prev = X;
    float* cur = tA;
    float* nxt[4] = {tB, tC, tA, tB};
    for (int k = 2; k < 6; k++) {
        float* nx = nxt[k - 2];
        run_L(Dm, V, eigs, cur, prev, nx, 1);
        gemm_small<1, 0><<<gs, 256>>>(nx, W + (size_t)k * 64 * Cout, nullptr, acc, N_V, Cout, 64);
        prev = cur; cur = nx;
    }
    bn_stats<<<Cout, 256>>>(acc, gam, bet, Cout);
    int total = N_V * Cout;
    bn_apply<<<(total + 255) / 256, 256>>>(acc, Yout, Cout, total);
}

extern "C" void kernel_launch(void* const* d_in, const int* in_sizes, int n_in,
                              void* d_out, int out_size) {
    const float* x     = (const float*)d_in[0];
    const float* V     = (const float*)d_in[1];
    const float* Dm    = (const float*)d_in[2];
    const float* eigs  = (const float*)d_in[3];
    const float* fc1_w = (const float*)d_in[4];
    const float* fc1_b = (const float*)d_in[5];
    const float* bf1_g = (const float*)d_in[6];
    const float* bf1_b = (const float*)d_in[7];
    const float* W1  = (const float*)d_in[8];
    const float* cb1 = (const float*)d_in[9];
    const float* b1g = (const float*)d_in[10];
    const float* b1b = (const float*)d_in[11];
    const float* W2  = (const float*)d_in[12];
    const float* cb2 = (const float*)d_in[13];
    const float* b2g = (const float*)d_in[14];
    const float* b2b = (const float*)d_in[15];
    const float* W3  = (const float*)d_in[16];
    const float* cb3 = (const float*)d_in[17];
    const float* b3g = (const float*)d_in[18];
    const float* b3b = (const float*)d_in[19];
    const float* fc2_w = (const float*)d_in[20];
    const float* fc2_b = (const float*)d_in[21];
    const float* bf2_g = (const float*)d_in[22];
    const float* bf2_b = (const float*)d_in[23];
    const float* fc3_w = (const float*)d_in[24];
    const float* fc3_b = (const float*)d_in[25];

    float* out  = (float*)d_out;
    float* desc = out + (size_t)N_V * N_V;   // outputs: [log_softmax | desc]

    float *acc, *h, *tA, *tB, *tC;
    cudaGetSymbolAddress((void**)&acc, g_acc);
    cudaGetSymbolAddress((void**)&h,   g_h);
    cudaGetSymbolAddress((void**)&tA,  g_tA);
    cudaGetSymbolAddress((void**)&tB,  g_tB);
    cudaGetSymbolAddress((void**)&tC,  g_tC);

    cudaFuncSetAttribute(fc3_kernel, cudaFuncAttributeMaxDynamicSharedMemorySize, SM_TOT);

    // fc3_w transpose + bf16 hi/lo split (independent; overlaps pipeline head)
    split_b_kernel<<<dim3((N_V + 31) / 32, 256 / 32), dim3(32, 32)>>>(fc3_w);

    // fc1 + BN + relu -> h[10000,64]
    {
        dim3 g1(1, (N_V + 63) / 64);
        gemm_small<0, 1><<<g1, 256>>>(x, fc1_w, fc1_b, acc, N_V, 64, IN_DESC);
        bn_stats<<<64, 256>>>(acc, bf1_g, bf1_b, 64);
        int total = N_V * 64;
        bn_apply<<<(total + 255) / 256, 256>>>(acc, h, 64, total);
    }

    // three Chebyshev spectral-conv layers (+BN+relu), in place on h
    run_cheb(h, W1, cb1, b1g, b1b, 64,  Dm, V, eigs, acc, tA, tB, tC, h);
    run_cheb(h, W2, cb2, b2g, b2b, 64,  Dm, V, eigs, acc, tA, tB, tC, h);
    run_cheb(h, W3, cb3, b3g, b3b, 128, Dm, V, eigs, acc, tA, tB, tC, h);

    // fc2 + BN + relu -> desc (written straight into d_out tail)
    {
        dim3 g2(256 / 64, (N_V + 63) / 64);
        gemm_small<0, 1><<<g2, 256>>>(h, fc2_w, fc2_b, acc, N_V, 256, 128);
        bn_stats<<<256, 256>>>(acc, bf2_g, bf2_b, 256);
        int total = N_V * 256;
        bn_apply<<<(total + 255) / 256, 256>>>(acc, desc, 256, total);
    }

    // desc bf16 hi/lo split, then fc3 via mma.sync bf16x3
    split_a_kernel<<<(N_V * 64 + 255) / 256, 256>>>(desc);
    {
        dim3 g3((N_V + 127) / 128, (N_V + 127) / 128);
        fc3_kernel<<<g3, 256, SM_TOT>>>(fc3_b, out);
    }

    // in-place row log-softmax
    lsm_kernel<<<N_V, 256>>>(out);
}

// round 7
// speedup vs baseline: 1.7693x; 1.2915x over previous
#include <cuda_runtime.h>
#include <cuda_bf16.h>
#include <math.h>
#include <stdint.h>

#define N_V 10000
#define NSPEC 64
#define IN_DESC 352
#define OUT_DESC 256

// ---------------- scratch (device globals; no allocations allowed) ----------
__device__ float g_acc[N_V * 256];   // pre-BN accumulator (max width 256: fc2)
__device__ float g_h[N_V * 128];     // current activations
__device__ float g_c0[NSPEC * 64];   // D @ X   [64,64]
__device__ float g_G[NSPEC * NSPEC]; // D @ V   [64,64]
__device__ float g_U[64 * 128];      // spectral weight combo [64,Cout]
__device__ float g_Wx[64 * 128];     // direct-X weight combo [64,Cout]
__device__ float g_scale[256];       // BN fused scale/shift
__device__ float g_shift[256];
__device__ __nv_bfloat16 g_bh[N_V * 256];  // fc3_w transposed [N,K], hi split
__device__ __nv_bfloat16 g_bl[N_V * 256];  // lo split
__device__ __nv_bfloat16 g_ah[N_V * 256];  // desc [M,K], hi split
__device__ __nv_bfloat16 g_al[N_V * 256];  // lo split

// ---------------- mma.sync helpers (base sm_103-legal) ----------------------
__device__ __forceinline__ uint32_t smem_u32(const void* p) {
    uint32_t a;
    asm("{ .reg .u64 t; cvta.to.shared.u64 t, %1; cvt.u32.u64 %0, t; }" : "=r"(a) : "l"(p));
    return a;
}
#define LDSM_X4(r0, r1, r2, r3, addr) \
    asm volatile("ldmatrix.sync.aligned.m8n8.x4.shared.b16 {%0,%1,%2,%3}, [%4];" \
        : "=r"(r0), "=r"(r1), "=r"(r2), "=r"(r3) : "r"(addr))
#define LDSM_X2(r0, r1, addr) \
    asm volatile("ldmatrix.sync.aligned.m8n8.x2.shared.b16 {%0,%1}, [%2];" \
        : "=r"(r0), "=r"(r1) : "r"(addr))
#define MMA_BF16(c, a, b) \
    asm volatile("mma.sync.aligned.m16n8k16.row.col.f32.bf16.bf16.f32 " \
        "{%0,%1,%2,%3}, {%4,%5,%6,%7}, {%8,%9}, {%0,%1,%2,%3};" \
        : "+f"((c)[0]), "+f"((c)[1]), "+f"((c)[2]), "+f"((c)[3]) \
        : "r"((a)[0]), "r"((a)[1]), "r"((a)[2]), "r"((a)[3]), "r"((b)[0]), "r"((b)[1]))

__device__ __forceinline__ uint32_t sw128(uint32_t off) {
    return off ^ ((off >> 3) & 0x70);
}
__device__ __forceinline__ uint32_t packb(__nv_bfloat16 a, __nv_bfloat16 b) {
    unsigned short ua = *reinterpret_cast<unsigned short*>(&a);
    unsigned short ub = *reinterpret_cast<unsigned short*>(&b);
    return (uint32_t)ua | ((uint32_t)ub << 16);
}

// ---------------- fc3_w pre-transpose + bf16 split: [K=256,N] -> [N,K] ------
__global__ void split_b_kernel(const float* __restrict__ W) {
    __shared__ float s[32][33];
    const int tx = threadIdx.x, ty = threadIdx.y;
    const int n0 = blockIdx.x * 32, k0 = blockIdx.y * 32;
    float v = 0.f;
    if (n0 + tx < N_V) v = W[(size_t)(k0 + ty) * N_V + n0 + tx];
    s[ty][tx] = v;
    __syncthreads();
    int n = n0 + ty;
    if (n < N_V) {
        float x = s[tx][ty];
        __nv_bfloat16 hb = __float2bfloat16(x);
        float r = x - __bfloat162float(hb);
        g_bh[(size_t)n * 256 + k0 + tx] = hb;
        g_bl[(size_t)n * 256 + k0 + tx] = __float2bfloat16(r);
    }
}

// ---------------- desc bf16 split: [M,K] fp32 -> hi/lo bf16 ------------------
__global__ void split_a_kernel(const float* __restrict__ A) {
    int i = blockIdx.x * 256 + threadIdx.x;
    if (i < N_V * 64) {
        float4 f = ((const float4*)A)[i];
        __nv_bfloat16 h0 = __float2bfloat16(f.x), h1 = __float2bfloat16(f.y);
        __nv_bfloat16 h2 = __float2bfloat16(f.z), h3 = __float2bfloat16(f.w);
        uint2 hv, lv;
        hv.x = packb(h0, h1); hv.y = packb(h2, h3);
        lv.x = packb(__float2bfloat16(f.x - __bfloat162float(h0)),
                     __float2bfloat16(f.y - __bfloat162float(h1)));
        lv.y = packb(__float2bfloat16(f.z - __bfloat162float(h2)),
                     __float2bfloat16(f.w - __bfloat162float(h3)));
        ((uint2*)g_ah)[i] = hv;
        ((uint2*)g_al)[i] = lv;
    }
}

// ---------------- fc3 GEMM via mma.sync bf16x3 (2 CTAs/SM) -------------------
#define SM_AH 0
#define SM_AL 16384
#define SM_BH 32768
#define SM_BL 49152
#define SM_TOT 65536

__global__ __launch_bounds__(256, 2)
void fc3_kernel(const float* __restrict__ bias, float* __restrict__ C) {
    extern __shared__ char smem[];
    const uint32_t sbase = smem_u32(smem);
    const int tid = threadIdx.x;
    const int wid = tid >> 5, lane = tid & 31;
    const int wm = wid >> 2, wn = wid & 3;
    const int row0 = blockIdx.y * 128, col0 = blockIdx.x * 128;

    float acc[4][4][4] = {};

    const int l15 = lane & 15;
    const uint32_t a_row = (uint32_t)(wm * 64 + l15);
    const uint32_t a_halfb = (uint32_t)((lane >> 4) * 16);
    const uint32_t b_row = (uint32_t)(wn * 32 + (l15 & 7));
    const uint32_t b_halfb = (uint32_t)((l15 >> 3) * 16);

    for (int kc = 0; kc < 4; kc++) {
        __syncthreads();
        const uint4 zero4 = make_uint4(0, 0, 0, 0);
        #pragma unroll
        for (int t = 0; t < 4; t++) {
            int i = tid + t * 256;
            int r = i >> 3, c = i & 7;
            uint32_t soff = sw128((uint32_t)(r * 128 + c * 16));
            size_t gb = (size_t)(row0 + r) * 512 + (size_t)kc * 128 + c * 16;
            uint4 vah = zero4, val = zero4;
            if (row0 + r < N_V) {
                vah = *(const uint4*)((const char*)g_ah + gb);
                val = *(const uint4*)((const char*)g_al + gb);
            }
            *(uint4*)(smem + SM_AH + soff) = vah;
            *(uint4*)(smem + SM_AL + soff) = val;
            size_t hb = (size_t)(col0 + r) * 512 + (size_t)kc * 128 + c * 16;
            uint4 vbh = zero4, vbl = zero4;
            if (col0 + r < N_V) {
                vbh = *(const uint4*)((const char*)g_bh + hb);
                vbl = *(const uint4*)((const char*)g_bl + hb);
            }
            *(uint4*)(smem + SM_BH + soff) = vbh;
            *(uint4*)(smem + SM_BL + soff) = vbl;
        }
        __syncthreads();

        #pragma unroll
        for (int ks = 0; ks < 4; ks++) {
            uint32_t ah[4][4], al[4][4], bh[4][2], bl[4][2];
            #pragma unroll
            for (int mt = 0; mt < 4; mt++) {
                uint32_t off = sw128((a_row + mt * 16) * 128 + ks * 32 + a_halfb);
                LDSM_X4(ah[mt][0], ah[mt][1], ah[mt][2], ah[mt][3], sbase + SM_AH + off);
                LDSM_X4(al[mt][0], al[mt][1], al[mt][2], al[mt][3], sbase + SM_AL + off);
            }
            #pragma unroll
            for (int nt = 0; nt < 4; nt++) {
                uint32_t off = sw128((b_row + nt * 8) * 128 + ks * 32 + b_halfb);
                LDSM_X2(bh[nt][0], bh[nt][1], sbase + SM_BH + off);
                LDSM_X2(bl[nt][0], bl[nt][1], sbase + SM_BL + off);
            }
            #pragma unroll
            for (int mt = 0; mt < 4; mt++)
                #pragma unroll
                for (int nt = 0; nt < 4; nt++) {
                    MMA_BF16(acc[mt][nt], ah[mt], bh[nt]);
                    MMA_BF16(acc[mt][nt], ah[mt], bl[nt]);
                    MMA_BF16(acc[mt][nt], al[mt], bh[nt]);
                }
        }
    }

    const int r_base = row0 + wm * 64 + (lane >> 2);
    const int c_base = col0 + wn * 32 + ((lane & 3) << 1);
    #pragma unroll
    for (int mt = 0; mt < 4; mt++) {
        #pragma unroll
        for (int nt = 0; nt < 4; nt++) {
            int cc = c_base + nt * 8;
            if (cc >= N_V) continue;
            float2 bb = *(const float2*)(bias + cc);
            int rr = r_base + mt * 16;
            if (rr < N_V) {
                float2 v = make_float2(acc[mt][nt][0] + bb.x, acc[mt][nt][1] + bb.y);
                *(float2*)(C + (size_t)rr * N_V + cc) = v;
            }
            if (rr + 8 < N_V) {
                float2 v = make_float2(acc[mt][nt][2] + bb.x, acc[mt][nt][3] + bb.y);
                *(float2*)(C + (size_t)(rr + 8) * N_V + cc) = v;
            }
        }
    }
}

// ---------------- small GEMM (fc1/fc2): C = A @ B --------------------------
template<int ACC, int BIAS>
__global__ void gemm_small(const float* __restrict__ A, const float* __restrict__ B,
                           const float* __restrict__ bias, float* __restrict__ C,
                           int M, int Nn, int K) {
    __shared__ float As[16][64];
    __shared__ float Bs[16][64];
    const int tid = threadIdx.x;
    const int ty = tid >> 4, tx = tid & 15;
    const int row0 = blockIdx.y * 64, col0 = blockIdx.x * 64;
    const int arow = tid >> 2, ak = (tid & 3) << 2;
    const int bk = tid >> 4, bcol = (tid & 15) << 2;
    float acc[4][4] = {};
    for (int k0 = 0; k0 < K; k0 += 16) {
        float4 av = make_float4(0.f, 0.f, 0.f, 0.f);
        if (row0 + arow < M)
            av = *(const float4*)(A + (size_t)(row0 + arow) * K + k0 + ak);
        As[ak + 0][arow] = av.x; As[ak + 1][arow] = av.y;
        As[ak + 2][arow] = av.z; As[ak + 3][arow] = av.w;
        float4 bv = *(const float4*)(B + (size_t)(k0 + bk) * Nn + col0 + bcol);
        *(float4*)(&Bs[bk][bcol]) = bv;
        __syncthreads();
        #pragma unroll
        for (int kk = 0; kk < 16; kk++) {
            float a[4], b[4];
            #pragma unroll
            for (int i = 0; i < 4; i++) a[i] = As[kk][ty * 4 + i];
            #pragma unroll
            for (int j = 0; j < 4; j++) b[j] = Bs[kk][tx * 4 + j];
            #pragma unroll
            for (int i = 0; i < 4; i++)
                #pragma unroll
                for (int j = 0; j < 4; j++)
                    acc[i][j] += a[i] * b[j];
        }
        __syncthreads();
    }
    #pragma unroll
    for (int i = 0; i < 4; i++) {
        int r = row0 + ty * 4 + i;
        if (r >= M) continue;
        #pragma unroll
        for (int j = 0; j < 4; j++) {
            int c = col0 + tx * 4 + j;
            float v = acc[i][j];
            if (BIAS) v += bias[c];
            if (ACC) v += C[(size_t)r * Nn + c];
            C[(size_t)r * Nn + c] = v;
        }
    }
}

// ---------------- 64x64 split-K reduce: out += D[64,N_V] @ Z[N_V,64] --------
__global__ void zero64(float* p) { p[blockIdx.x * 256 + threadIdx.x] = 0.f; }

__global__ void dmat_kernel(const float* __restrict__ Dm, const float* __restrict__ Z,
                            float* __restrict__ outp) {
    __shared__ float sD[4][64];
    __shared__ float sZ[4][64];
    const int tid = threadIdx.x;
    const int i4 = (tid >> 4) << 2;
    const int j4 = (tid & 15) << 2;
    float acc[4][4] = {};
    const int nb0 = blockIdx.x * 80;
    for (int nb = 0; nb < 80; nb += 4) {
        const int nbase = nb0 + nb;
        {
            int ii = tid >> 2, nn = tid & 3;
            sD[nn][ii] = Dm[(size_t)ii * N_V + nbase + nn];
            sZ[tid >> 6][tid & 63] = Z[(size_t)(nbase + (tid >> 6)) * 64 + (tid & 63)];
        }
        __syncthreads();
        #pragma unroll
        for (int nn = 0; nn < 4; nn++) {
            float d[4], z[4];
            #pragma unroll
            for (int a = 0; a < 4; a++) d[a] = sD[nn][i4 + a];
            #pragma unroll
            for (int b = 0; b < 4; b++) z[b] = sZ[nn][j4 + b];
            #pragma unroll
            for (int a = 0; a < 4; a++)
                #pragma unroll
                for (int b = 0; b < 4; b++)
                    acc[a][b] += d[a] * z[b];
        }
        __syncthreads();
    }
    #pragma unroll
    for (int a = 0; a < 4; a++)
        #pragma unroll
        for (int b = 0; b < 4; b++)
            atomicAdd(&outp[(i4 + a) * 64 + j4 + b], acc[a][b]);
}

// ---------------- spectral Chebyshev recurrence (one block) ------------------
// Computes U = sum_{k>=1} s_k W_k  and  Wx = W0 - W2 + W4,  where
// s1 = e*c0; c_k = G s_k + alpha_k c0; s_{k+1} = 2 e*c_k - s_{k-1}.
template<int COUT>
__global__ void spectral_kernel(const float* __restrict__ W,
                                const float* __restrict__ eigs) {
    extern __shared__ float sm[];
    float* G   = sm;              // 4096
    float* c0  = G + 4096;        // 4096
    float* bufA = c0 + 4096;      // s_prev
    float* bufB = bufA + 4096;    // s_cur
    float* ck  = bufB + 4096;     // 4096
    float* U   = ck + 4096;       // 64*COUT
    float* sW  = U + 64 * COUT;   // 64*COUT
    __shared__ float e[64];
    const int tid = threadIdx.x;
    const int T = blockDim.x;
    for (int i = tid; i < 4096; i += T) { G[i] = g_G[i]; c0[i] = g_c0[i]; }
    if (tid < 64) e[tid] = eigs[tid];
    __syncthreads();
    for (int i = tid; i < 4096; i += T) { bufA[i] = 0.f; bufB[i] = e[i >> 6] * c0[i]; }
    for (int i = tid; i < 64 * COUT; i += T) sW[i] = W[64 * COUT + i];  // W1
    __syncthreads();
    for (int i = tid; i < 64 * COUT; i += T) {
        int r = i / COUT, c = i % COUT;
        float s = 0.f;
        #pragma unroll 8
        for (int m = 0; m < 64; m++) s += bufB[r * 64 + m] * sW[m * COUT + c];
        U[i] = s;
    }
    float* sp = bufA;
    float* sc = bufB;
    for (int k = 1; k <= 4; k++) {
        __syncthreads();
        const float a = (k == 2) ? -1.f : ((k == 4) ? 1.f : 0.f);
        for (int i = tid; i < 4096; i += T) {
            int r = i >> 6, c = i & 63;
            float s = 0.f;
            #pragma unroll 8
            for (int m = 0; m < 64; m++) s += G[r * 64 + m] * sc[m * 64 + c];
            ck[i] = s + a * c0[i];
        }
        __syncthreads();
        for (int i = tid; i < 4096; i += T) sp[i] = 2.f * e[i >> 6] * ck[i] - sp[i];
        for (int i = tid; i < 64 * COUT; i += T) sW[i] = W[(size_t)(k + 1) * 64 * COUT + i];
        __syncthreads();
        for (int i = tid; i < 64 * COUT; i += T) {
            int r = i / COUT, c = i % COUT;
            float s = 0.f;
            #pragma unroll 8
            for (int m = 0; m < 64; m++) s += sp[r * 64 + m] * sW[m * COUT + c];
            U[i] += s;
        }
        float* t = sp; sp = sc; sc = t;
    }
    __syncthreads();
    for (int i = tid; i < 64 * COUT; i += T) {
        g_U[i] = U[i];
        g_Wx[i] = W[i] - W[2 * 64 * COUT + i] + W[4 * 64 * COUT + i];
    }
}

// ---------------- cheb output: out = X @ Wx + V @ U --------------------------
template<int COUT>
__global__ void chebout_kernel(const float* __restrict__ X, const float* __restrict__ Vm,
                               float* __restrict__ outp) {
    constexpr int TPR = COUT / 32;
    constexpr int ROWS = 256 / TPR;
    extern __shared__ float sm[];
    float* sWx = sm;                  // 64*COUT
    float* sU  = sWx + 64 * COUT;     // 64*COUT
    float* sX  = sU + 64 * COUT;      // ROWS*64
    float* sV  = sX + ROWS * 64;      // ROWS*64
    const int tid = threadIdx.x;
    for (int i = tid; i < 64 * COUT; i += 256) { sWx[i] = g_Wx[i]; sU[i] = g_U[i]; }
    const int row0 = blockIdx.x * ROWS;
    for (int i = tid; i < ROWS * 16; i += 256) {
        int r = i >> 4, q = i & 15;
        int gr = row0 + r;
        float4 xv = make_float4(0.f, 0.f, 0.f, 0.f), vv = xv;
        if (gr < N_V) {
            xv = *(const float4*)(X + (size_t)gr * 64 + q * 4);
            vv = *(const float4*)(Vm + (size_t)gr * 64 + q * 4);
        }
        *(float4*)(sX + r * 64 + q * 4) = xv;
        *(float4*)(sV + r * 64 + q * 4) = vv;
    }
    __syncthreads();
    const int lr = tid / TPR;
    const int j0 = (tid % TPR) * 32;
    const int gr = row0 + lr;
    float acc[32] = {};
    #pragma unroll 4
    for (int k = 0; k < 64; k++) {
        float a = sX[lr * 64 + k];
        #pragma unroll
        for (int j = 0; j < 32; j++) acc[j] += a * sWx[k * COUT + j0 + j];
    }
    #pragma unroll 4
    for (int k = 0; k < 64; k++) {
        float v = sV[lr * 64 + k];
        #pragma unroll
        for (int j = 0; j < 32; j++) acc[j] += v * sU[k * COUT + j0 + j];
    }
    if (gr < N_V) {
        float* o = outp + (size_t)gr * COUT + j0;
        #pragma unroll
        for (int j = 0; j < 32; j++) o[j] = acc[j];
    }
}

// ---------------- BatchNorm ---------------------------------------------------
__global__ void bn_stats(const float* __restrict__ X, const float* __restrict__ gam,
                         const float* __restrict__ bet, int C) {
    __shared__ float s1[256], s2v[256];
    const int c = blockIdx.x, tid = threadIdx.x;
    float s = 0.f, s2 = 0.f;
    for (int r = tid; r < N_V; r += 256) {
        float v = X[(size_t)r * C + c];
        s += v; s2 += v * v;
    }
    s1[tid] = s; s2v[tid] = s2;
    __syncthreads();
    for (int st = 128; st > 0; st >>= 1) {
        if (tid < st) { s1[tid] += s1[tid + st]; s2v[tid] += s2v[tid + st]; }
        __syncthreads();
    }
    if (tid == 0) {
        float mean = s1[0] * (1.f / N_V);
        float var = s2v[0] * (1.f / N_V) - mean * mean;
        float istd = rsqrtf(var + 1e-3f);
        float sc = gam[c] * istd;
        g_scale[c] = sc;
        g_shift[c] = bet[c] - mean * sc;
    }
}

__global__ void bn_apply(const float* __restrict__ X, float* __restrict__ Y,
                         int C, int total) {
    int i = blockIdx.x * 256 + threadIdx.x;
    if (i < total) {
        int c = i & (C - 1);
        Y[i] = fmaxf(fmaf(X[i], g_scale[c], g_shift[c]), 0.f);
    }
}

// ---------------- in-place row log-softmax (float4) --------------------------
__global__ void lsm_kernel(float* __restrict__ out) {
    __shared__ float srow[N_V];
    __shared__ float red[256];
    const int row = blockIdx.x, tid = threadIdx.x;
    float4* p4 = (float4*)(out + (size_t)row * N_V);
    float4* s4 = (float4*)srow;
    float m = -1e30f;
    for (int i = tid; i < N_V / 4; i += 256) {
        float4 v = p4[i];
        s4[i] = v;
        m = fmaxf(m, fmaxf(fmaxf(v.x, v.y), fmaxf(v.z, v.w)));
    }
    red[tid] = m;
    __syncthreads();
    for (int st = 128; st > 0; st >>= 1) {
        if (tid < st) red[tid] = fmaxf(red[tid], red[tid + st]);
        __syncthreads();
    }
    m = red[0];
    __syncthreads();
    float s = 0.f;
    for (int i = tid; i < N_V; i += 256) s += __expf(srow[i] - m);
    red[tid] = s;
    __syncthreads();
    for (int st = 128; st > 0; st >>= 1) {
        if (tid < st) red[tid] += red[tid + st];
        __syncthreads();
    }
    float lse = m + logf(red[0]);
    for (int i = tid; i < N_V / 4; i += 256) {
        float4 v = s4[i];
        v.x -= lse; v.y -= lse; v.z -= lse; v.w -= lse;
        p4[i] = v;
    }
}

// ---------------- host orchestration ----------------------------------------
extern "C" void kernel_launch(void* const* d_in, const int* in_sizes, int n_in,
                              void* d_out, int out_size) {
    const float* x     = (const float*)d_in[0];
    const float* V     = (const float*)d_in[1];
    const float* Dm    = (const float*)d_in[2];
    const float* eigs  = (const float*)d_in[3];
    const float* fc1_w = (const float*)d_in[4];
    const float* bf1_g = (const float*)d_in[6];
    const float* bf1_b = (const float*)d_in[7];
    const float* W1  = (const float*)d_in[8];
    const float* b1g = (const float*)d_in[10];
    const float* b1b = (const float*)d_in[11];
    const float* W2  = (const float*)d_in[12];
    const float* b2g = (const float*)d_in[14];
    const float* b2b = (const float*)d_in[15];
    const float* W3  = (const float*)d_in[16];
    const float* b3g = (const float*)d_in[18];
    const float* b3b = (const float*)d_in[19];
    const float* fc2_w = (const float*)d_in[20];
    const float* bf2_g = (const float*)d_in[22];
    const float* bf2_b = (const float*)d_in[23];
    const float* fc3_w = (const float*)d_in[24];
    const float* fc3_b = (const float*)d_in[25];

    float* out  = (float*)d_out;
    float* desc = out + (size_t)N_V * N_V;   // outputs: [log_softmax | desc]

    float *acc, *h, *c0, *G;
    cudaGetSymbolAddress((void**)&acc, g_acc);
    cudaGetSymbolAddress((void**)&h,   g_h);
    cudaGetSymbolAddress((void**)&c0,  g_c0);
    cudaGetSymbolAddress((void**)&G,   g_G);

    static bool attr_done = false;
    if (!attr_done) {
        cudaFuncSetAttribute(fc3_kernel, cudaFuncAttributeMaxDynamicSharedMemorySize, SM_TOT);
        cudaFuncSetAttribute(spectral_kernel<64>,  cudaFuncAttributeMaxDynamicSharedMemorySize, (5 * 4096 + 2 * 64 * 64) * 4);
        cudaFuncSetAttribute(spectral_kernel<128>, cudaFuncAttributeMaxDynamicSharedMemorySize, (5 * 4096 + 2 * 64 * 128) * 4);
        cudaFuncSetAttribute(chebout_kernel<64>,  cudaFuncAttributeMaxDynamicSharedMemorySize, 98304);
        cudaFuncSetAttribute(chebout_kernel<128>, cudaFuncAttributeMaxDynamicSharedMemorySize, 98304);
        attr_done = true;
    }

    // independent prep: G = D @ V, fc3_w transpose+split
    zero64<<<16, 256>>>(G);
    dmat_kernel<<<125, 256>>>(Dm, V, G);
    split_b_kernel<<<dim3((N_V + 31) / 32, 256 / 32), dim3(32, 32)>>>(fc3_w);

    // fc1 + BN + relu -> h[10000,64]   (bias cancels in BN)
    {
        dim3 g1(1, (N_V + 63) / 64);
        gemm_small<0, 0><<<g1, 256>>>(x, fc1_w, nullptr, acc, N_V, 64, IN_DESC);
        bn_stats<<<64, 256>>>(acc, bf1_g, bf1_b, 64);
        bn_apply<<<(N_V * 64 + 255) / 256, 256>>>(acc, h, 64, N_V * 64);
    }

    // cheb layer 1 (Cout=64)
    zero64<<<16, 256>>>(c0);
    dmat_kernel<<<125, 256>>>(Dm, h, c0);
    spectral_kernel<64><<<1, 512, (5 * 4096 + 2 * 64 * 64) * 4>>>(W1, eigs);
    chebout_kernel<64><<<(N_V + 127) / 128, 256, 98304>>>(h, V, acc);
    bn_stats<<<64, 256>>>(acc, b1g, b1b, 64);
    bn_apply<<<(N_V * 64 + 255) / 256, 256>>>(acc, h, 64, N_V * 64);

    // cheb layer 2 (Cout=64)
    zero64<<<16, 256>>>(c0);
    dmat_kernel<<<125, 256>>>(Dm, h, c0);
    spectral_kernel<64><<<1, 512, (5 * 4096 + 2 * 64 * 64) * 4>>>(W2, eigs);
    chebout_kernel<64><<<(N_V + 127) / 128, 256, 98304>>>(h, V, acc);
    bn_stats<<<64, 256>>>(acc, b2g, b2b, 64);
    bn_apply<<<(N_V * 64 + 255) / 256, 256>>>(acc, h, 64, N_V * 64);

    // cheb layer 3 (Cout=128)
    zero64<<<16, 256>>>(c0);
    dmat_kernel<<<125, 256>>>(Dm, h, c0);
    spectral_kernel<128><<<1, 512, (5 * 4096 + 2 * 64 * 128) * 4>>>(W3, eigs);
    chebout_kernel<128><<<(N_V + 63) / 64, 256, 98304>>>(h, V, acc);
    bn_stats<<<128, 256>>>(acc, b3g, b3b, 128);
    bn_apply<<<(N_V * 128 + 255) / 256, 256>>>(acc, h, 128, N_V * 128);

    // fc2 + BN + relu -> desc
    {
        dim3 g2(256 / 64, (N_V + 63) / 64);
        gemm_small<0, 0><<<g2, 256>>>(h, fc2_w, nullptr, acc, N_V, 256, 128);
        bn_stats<<<256, 256>>>(acc, bf2_g, bf2_b, 256);
        bn_apply<<<(N_V * 256 + 255) / 256, 256>>>(acc, desc, 256, N_V * 256);
    }

    // desc split + fc3 (mma.sync bf16x3)
    split_a_kernel<<<(N_V * 64 + 255) / 256, 256>>>(desc);
    {
        dim3 g3((N_V + 127) / 128, (N_V + 127) / 128);
        fc3_kernel<<<g3, 256, SM_TOT>>>(fc3_b, out);
    }

    // in-place row log-softmax
    lsm_kernel<<<N_V, 256>>>(out);
}

// round 8
// speedup vs baseline: 2.0220x; 1.1428x over previous
#include <cuda_runtime.h>
#include <cuda_fp16.h>
#include <math.h>
#include <stdint.h>

#define N_V 10000
#define NSPEC 64
#define IN_DESC 352
#define OUT_DESC 256

// ---------------- scratch (device globals; no allocations allowed) ----------
__device__ float g_acc[N_V * 256];   // pre-BN accumulator (max width 256: fc2)
__device__ float g_h[N_V * 128];     // current activations
__device__ float g_c0[NSPEC * 64];   // D @ X   [64,64]
__device__ float g_G[NSPEC * NSPEC]; // D @ V   [64,64]
__device__ float g_U[64 * 128];      // spectral weight combo [64,Cout]
__device__ float g_Wx[64 * 128];     // direct-X weight combo [64,Cout]
__device__ float g_scale[256];       // BN fused scale/shift
__device__ float g_shift[256];
__device__ __half g_bw[N_V * 256];   // fc3_w transposed [N,K] fp16
__device__ __half g_aw[N_V * 256];   // desc [M,K] fp16

// ---------------- mma.sync helpers (base sm_103-legal) ----------------------
__device__ __forceinline__ uint32_t smem_u32(const void* p) {
    uint32_t a;
    asm("{ .reg .u64 t; cvta.to.shared.u64 t, %1; cvt.u32.u64 %0, t; }" : "=r"(a) : "l"(p));
    return a;
}
#define LDSM_X4(r0, r1, r2, r3, addr) \
    asm volatile("ldmatrix.sync.aligned.m8n8.x4.shared.b16 {%0,%1,%2,%3}, [%4];" \
        : "=r"(r0), "=r"(r1), "=r"(r2), "=r"(r3) : "r"(addr))
#define LDSM_X2(r0, r1, addr) \
    asm volatile("ldmatrix.sync.aligned.m8n8.x2.shared.b16 {%0,%1}, [%2];" \
        : "=r"(r0), "=r"(r1) : "r"(addr))
#define MMA_F16(c, a, b) \
    asm volatile("mma.sync.aligned.m16n8k16.row.col.f32.f16.f16.f32 " \
        "{%0,%1,%2,%3}, {%4,%5,%6,%7}, {%8,%9}, {%0,%1,%2,%3};" \
        : "+f"((c)[0]), "+f"((c)[1]), "+f"((c)[2]), "+f"((c)[3]) \
        : "r"((a)[0]), "r"((a)[1]), "r"((a)[2]), "r"((a)[3]), "r"((b)[0]), "r"((b)[1]))

__device__ __forceinline__ uint32_t sw128(uint32_t off) {
    return off ^ ((off >> 3) & 0x70);
}
__device__ __forceinline__ uint32_t packh(__half a, __half b) {
    unsigned short ua = *reinterpret_cast<unsigned short*>(&a);
    unsigned short ub = *reinterpret_cast<unsigned short*>(&b);
    return (uint32_t)ua | ((uint32_t)ub << 16);
}

// ---------------- fc3_w pre-transpose + fp16: [K=256,N] -> [N,K] ------------
__global__ void split_b_kernel(const float* __restrict__ W) {
    __shared__ float s[32][33];
    const int tx = threadIdx.x, ty = threadIdx.y;
    const int n0 = blockIdx.x * 32, k0 = blockIdx.y * 32;
    float v = 0.f;
    if (n0 + tx < N_V) v = W[(size_t)(k0 + ty) * N_V + n0 + tx];
    s[ty][tx] = v;
    __syncthreads();
    int n = n0 + ty;
    if (n < N_V) g_bw[(size_t)n * 256 + k0 + tx] = __float2half(s[tx][ty]);
}

// ---------------- desc fp16 convert: [M,K] fp32 -> fp16 ----------------------
__global__ void split_a_kernel(const float* __restrict__ A) {
    int i = blockIdx.x * 256 + threadIdx.x;
    if (i < N_V * 64) {
        float4 f = ((const float4*)A)[i];
        uint2 hv;
        hv.x = packh(__float2half(f.x), __float2half(f.y));
        hv.y = packh(__float2half(f.z), __float2half(f.w));
        ((uint2*)g_aw)[i] = hv;
    }
}

// ---------------- fc3 GEMM via mma.sync fp16 single-pass ---------------------
// C[10000,10000] = A[10000,256] @ B[N,K]^T + bias
// CTA: 128x128 tile, 8 warps (2m x 4n), warp tile 64x32, K chunk 64.
#define SM_A 0
#define SM_B 16384
#define SM_TOT 32768

__global__ __launch_bounds__(256, 2)
void fc3_kernel(const float* __restrict__ bias, float* __restrict__ C) {
    extern __shared__ char smem[];
    const uint32_t sbase = smem_u32(smem);
    const int tid = threadIdx.x;
    const int wid = tid >> 5, lane = tid & 31;
    const int wm = wid >> 2, wn = wid & 3;
    const int row0 = blockIdx.y * 128, col0 = blockIdx.x * 128;

    float acc[4][4][4] = {};

    const int l15 = lane & 15;
    const uint32_t a_row = (uint32_t)(wm * 64 + l15);
    const uint32_t a_halfb = (uint32_t)((lane >> 4) * 16);
    const uint32_t b_row = (uint32_t)(wn * 32 + (l15 & 7));
    const uint32_t b_halfb = (uint32_t)((l15 >> 3) * 16);

    for (int kc = 0; kc < 4; kc++) {
        __syncthreads();
        const uint4 zero4 = make_uint4(0, 0, 0, 0);
        #pragma unroll
        for (int t = 0; t < 4; t++) {
            int i = tid + t * 256;                 // 0..1023
            int r = i >> 3, c = i & 7;             // row, 16B chunk
            uint32_t soff = sw128((uint32_t)(r * 128 + c * 16));
            size_t gb = (size_t)(row0 + r) * 512 + (size_t)kc * 128 + c * 16;
            uint4 va = zero4;
            if (row0 + r < N_V) va = *(const uint4*)((const char*)g_aw + gb);
            *(uint4*)(smem + SM_A + soff) = va;
            size_t hb = (size_t)(col0 + r) * 512 + (size_t)kc * 128 + c * 16;
            uint4 vb = zero4;
            if (col0 + r < N_V) vb = *(const uint4*)((const char*)g_bw + hb);
            *(uint4*)(smem + SM_B + soff) = vb;
        }
        __syncthreads();

        #pragma unroll
        for (int ks = 0; ks < 4; ks++) {
            uint32_t af[4][4], bf[4][2];
            #pragma unroll
            for (int mt = 0; mt < 4; mt++) {
                uint32_t off = sw128((a_row + mt * 16) * 128 + ks * 32 + a_halfb);
                LDSM_X4(af[mt][0], af[mt][1], af[mt][2], af[mt][3], sbase + SM_A + off);
            }
            #pragma unroll
            for (int nt = 0; nt < 4; nt++) {
                uint32_t off = sw128((b_row + nt * 8) * 128 + ks * 32 + b_halfb);
                LDSM_X2(bf[nt][0], bf[nt][1], sbase + SM_B + off);
            }
            #pragma unroll
            for (int mt = 0; mt < 4; mt++)
                #pragma unroll
                for (int nt = 0; nt < 4; nt++)
                    MMA_F16(acc[mt][nt], af[mt], bf[nt]);
        }
    }

    const int r_base = row0 + wm * 64 + (lane >> 2);
    const int c_base = col0 + wn * 32 + ((lane & 3) << 1);
    #pragma unroll
    for (int mt = 0; mt < 4; mt++) {
        #pragma unroll
        for (int nt = 0; nt < 4; nt++) {
            int cc = c_base + nt * 8;
            if (cc >= N_V) continue;
            float2 bb = *(const float2*)(bias + cc);
            int rr = r_base + mt * 16;
            if (rr < N_V) {
                float2 v = make_float2(acc[mt][nt][0] + bb.x, acc[mt][nt][1] + bb.y);
                *(float2*)(C + (size_t)rr * N_V + cc) = v;
            }
            if (rr + 8 < N_V) {
                float2 v = make_float2(acc[mt][nt][2] + bb.x, acc[mt][nt][3] + bb.y);
                *(float2*)(C + (size_t)(rr + 8) * N_V + cc) = v;
            }
        }
    }
}

// ---------------- small GEMM (fc1/fc2): C = A @ B ----------------------------
template<int ACC, int BIAS>
__global__ void gemm_small(const float* __restrict__ A, const float* __restrict__ B,
                           const float* __restrict__ bias, float* __restrict__ C,
                           int M, int Nn, int K) {
    __shared__ float As[16][64];
    __shared__ float Bs[16][64];
    const int tid = threadIdx.x;
    const int ty = tid >> 4, tx = tid & 15;
    const int row0 = blockIdx.y * 64, col0 = blockIdx.x * 64;
    const int arow = tid >> 2, ak = (tid & 3) << 2;
    const int bk = tid >> 4, bcol = (tid & 15) << 2;
    float acc[4][4] = {};
    for (int k0 = 0; k0 < K; k0 += 16) {
        float4 av = make_float4(0.f, 0.f, 0.f, 0.f);
        if (row0 + arow < M)
            av = *(const float4*)(A + (size_t)(row0 + arow) * K + k0 + ak);
        As[ak + 0][arow] = av.x; As[ak + 1][arow] = av.y;
        As[ak + 2][arow] = av.z; As[ak + 3][arow] = av.w;
        float4 bv = *(const float4*)(B + (size_t)(k0 + bk) * Nn + col0 + bcol);
        *(float4*)(&Bs[bk][bcol]) = bv;
        __syncthreads();
        #pragma unroll
        for (int kk = 0; kk < 16; kk++) {
            float a[4], b[4];
            #pragma unroll
            for (int i = 0; i < 4; i++) a[i] = As[kk][ty * 4 + i];
            #pragma unroll
            for (int j = 0; j < 4; j++) b[j] = Bs[kk][tx * 4 + j];
            #pragma unroll
            for (int i = 0; i < 4; i++)
                #pragma unroll
                for (int j = 0; j < 4; j++)
                    acc[i][j] += a[i] * b[j];
        }
        __syncthreads();
    }
    #pragma unroll
    for (int i = 0; i < 4; i++) {
        int r = row0 + ty * 4 + i;
        if (r >= M) continue;
        #pragma unroll
        for (int j = 0; j < 4; j++) {
            int c = col0 + tx * 4 + j;
            float v = acc[i][j];
            if (BIAS) v += bias[c];
            if (ACC) v += C[(size_t)r * Nn + c];
            C[(size_t)r * Nn + c] = v;
        }
    }
}

// ---------------- 64x64 split-K reduce: out += D[64,N_V] @ Z[N_V,64] --------
__global__ void zero64(float* p) { p[blockIdx.x * 256 + threadIdx.x] = 0.f; }

__global__ void dmat_kernel(const float* __restrict__ Dm, const float* __restrict__ Z,
                            float* __restrict__ outp) {
    __shared__ float sD[4][64];
    __shared__ float sZ[4][64];
    const int tid = threadIdx.x;
    const int i4 = (tid >> 4) << 2;
    const int j4 = (tid & 15) << 2;
    float acc[4][4] = {};
    const int nb0 = blockIdx.x * 80;
    for (int nb = 0; nb < 80; nb += 4) {
        const int nbase = nb0 + nb;
        {
            int ii = tid >> 2, nn = tid & 3;
            sD[nn][ii] = Dm[(size_t)ii * N_V + nbase + nn];
            sZ[tid >> 6][tid & 63] = Z[(size_t)(nbase + (tid >> 6)) * 64 + (tid & 63)];
        }
        __syncthreads();
        #pragma unroll
        for (int nn = 0; nn < 4; nn++) {
            float d[4], z[4];
            #pragma unroll
            for (int a = 0; a < 4; a++) d[a] = sD[nn][i4 + a];
            #pragma unroll
            for (int b = 0; b < 4; b++) z[b] = sZ[nn][j4 + b];
            #pragma unroll
            for (int a = 0; a < 4; a++)
                #pragma unroll
                for (int b = 0; b < 4; b++)
                    acc[a][b] += d[a] * z[b];
        }
        __syncthreads();
    }
    #pragma unroll
    for (int a = 0; a < 4; a++)
        #pragma unroll
        for (int b = 0; b < 4; b++)
            atomicAdd(&outp[(i4 + a) * 64 + j4 + b], acc[a][b]);
}

// ---------------- spectral Chebyshev recurrence (one block) ------------------
template<int COUT>
__global__ void spectral_kernel(const float* __restrict__ W,
                                const float* __restrict__ eigs) {
    extern __shared__ float sm[];
    float* G   = sm;
    float* c0  = G + 4096;
    float* bufA = c0 + 4096;
    float* bufB = bufA + 4096;
    float* ck  = bufB + 4096;
    float* U   = ck + 4096;
    float* sW  = U + 64 * COUT;
    __shared__ float e[64];
    const int tid = threadIdx.x;
    const int T = blockDim.x;
    for (int i = tid; i < 4096; i += T) { G[i] = g_G[i]; c0[i] = g_c0[i]; }
    if (tid < 64) e[tid] = eigs[tid];
    __syncthreads();
    for (int i = tid; i < 4096; i += T) { bufA[i] = 0.f; bufB[i] = e[i >> 6] * c0[i]; }
    for (int i = tid; i < 64 * COUT; i += T) sW[i] = W[64 * COUT + i];
    __syncthreads();
    for (int i = tid; i < 64 * COUT; i += T) {
        int r = i / COUT, c = i % COUT;
        float s = 0.f;
        #pragma unroll 8
        for (int m = 0; m < 64; m++) s += bufB[r * 64 + m] * sW[m * COUT + c];
        U[i] = s;
    }
    float* sp = bufA;
    float* sc = bufB;
    for (int k = 1; k <= 4; k++) {
        __syncthreads();
        const float a = (k == 2) ? -1.f : ((k == 4) ? 1.f : 0.f);
        for (int i = tid; i < 4096; i += T) {
            int r = i >> 6, c = i & 63;
            float s = 0.f;
            #pragma unroll 8
            for (int m = 0; m < 64; m++) s += G[r * 64 + m] * sc[m * 64 + c];
            ck[i] = s + a * c0[i];
        }
        __syncthreads();
        for (int i = tid; i < 4096; i += T) sp[i] = 2.f * e[i >> 6] * ck[i] - sp[i];
        for (int i = tid; i < 64 * COUT; i += T) sW[i] = W[(size_t)(k + 1) * 64 * COUT + i];
        __syncthreads();
        for (int i = tid; i < 64 * COUT; i += T) {
            int r = i / COUT, c = i % COUT;
            float s = 0.f;
            #pragma unroll 8
            for (int m = 0; m < 64; m++) s += sp[r * 64 + m] * sW[m * COUT + c];
            U[i] += s;
        }
        float* t = sp; sp = sc; sc = t;
    }
    __syncthreads();
    for (int i = tid; i < 64 * COUT; i += T) {
        g_U[i] = U[i];
        g_Wx[i] = W[i] - W[2 * 64 * COUT + i] + W[4 * 64 * COUT + i];
    }
}

// ---------------- cheb output: out = X @ Wx + V @ U --------------------------
template<int COUT>
__global__ void chebout_kernel(const float* __restrict__ X, const float* __restrict__ Vm,
                               float* __restrict__ outp) {
    constexpr int TPR = COUT / 32;
    constexpr int ROWS = 256 / TPR;
    extern __shared__ float sm[];
    float* sWx = sm;
    float* sU  = sWx + 64 * COUT;
    float* sX  = sU + 64 * COUT;
    float* sV  = sX + ROWS * 64;
    const int tid = threadIdx.x;
    for (int i = tid; i < 64 * COUT; i += 256) { sWx[i] = g_Wx[i]; sU[i] = g_U[i]; }
    const int row0 = blockIdx.x * ROWS;
    for (int i = tid; i < ROWS * 16; i += 256) {
        int r = i >> 4, q = i & 15;
        int gr = row0 + r;
        float4 xv = make_float4(0.f, 0.f, 0.f, 0.f), vv = xv;
        if (gr < N_V) {
            xv = *(const float4*)(X + (size_t)gr * 64 + q * 4);
            vv = *(const float4*)(Vm + (size_t)gr * 64 + q * 4);
        }
        *(float4*)(sX + r * 64 + q * 4) = xv;
        *(float4*)(sV + r * 64 + q * 4) = vv;
    }
    __syncthreads();
    const int lr = tid / TPR;
    const int j0 = (tid % TPR) * 32;
    const int gr = row0 + lr;
    float acc[32] = {};
    #pragma unroll 4
    for (int k = 0; k < 64; k++) {
        float a = sX[lr * 64 + k];
        #pragma unroll
        for (int j = 0; j < 32; j++) acc[j] += a * sWx[k * COUT + j0 + j];
    }
    #pragma unroll 4
    for (int k = 0; k < 64; k++) {
        float v = sV[lr * 64 + k];
        #pragma unroll
        for (int j = 0; j < 32; j++) acc[j] += v * sU[k * COUT + j0 + j];
    }
    if (gr < N_V) {
        float* o = outp + (size_t)gr * COUT + j0;
        #pragma unroll
        for (int j = 0; j < 32; j++) o[j] = acc[j];
    }
}

// ---------------- BatchNorm ---------------------------------------------------
__global__ void bn_stats(const float* __restrict__ X, const float* __restrict__ gam,
                         const float* __restrict__ bet, int C) {
    __shared__ float s1[256], s2v[256];
    const int c = blockIdx.x, tid = threadIdx.x;
    float s = 0.f, s2 = 0.f;
    for (int r = tid; r < N_V; r += 256) {
        float v = X[(size_t)r * C + c];
        s += v; s2 += v * v;
    }
    s1[tid] = s; s2v[tid] = s2;
    __syncthreads();
    for (int st = 128; st > 0; st >>= 1) {
        if (tid < st) { s1[tid] += s1[tid + st]; s2v[tid] += s2v[tid + st]; }
        __syncthreads();
    }
    if (tid == 0) {
        float mean = s1[0] * (1.f / N_V);
        float var = s2v[0] * (1.f / N_V) - mean * mean;
        float istd = rsqrtf(var + 1e-3f);
        float sc = gam[c] * istd;
        g_scale[c] = sc;
        g_shift[c] = bet[c] - mean * sc;
    }
}

__global__ void bn_apply(const float* __restrict__ X, float* __restrict__ Y,
                         int C, int total) {
    int i = blockIdx.x * 256 + threadIdx.x;
    if (i < total) {
        int c = i & (C - 1);
        Y[i] = fmaxf(fmaf(X[i], g_scale[c], g_shift[c]), 0.f);
    }
}

// ---------------- in-place row log-softmax (float4) --------------------------
__global__ void lsm_kernel(float* __restrict__ out) {
    __shared__ float srow[N_V];
    __shared__ float red[256];
    const int row = blockIdx.x, tid = threadIdx.x;
    float4* p4 = (float4*)(out + (size_t)row * N_V);
    float4* s4 = (float4*)srow;
    float m = -1e30f;
    for (int i = tid; i < N_V / 4; i += 256) {
        float4 v = p4[i];
        s4[i] = v;
        m = fmaxf(m, fmaxf(fmaxf(v.x, v.y), fmaxf(v.z, v.w)));
    }
    red[tid] = m;
    __syncthreads();
    for (int st = 128; st > 0; st >>= 1) {
        if (tid < st) red[tid] = fmaxf(red[tid], red[tid + st]);
        __syncthreads();
    }
    m = red[0];
    __syncthreads();
    float s = 0.f;
    for (int i = tid; i < N_V; i += 256) s += __expf(srow[i] - m);
    red[tid] = s;
    __syncthreads();
    for (int st = 128; st > 0; st >>= 1) {
        if (tid < st) red[tid] += red[tid + st];
        __syncthreads();
    }
    float lse = m + logf(red[0]);
    for (int i = tid; i < N_V / 4; i += 256) {
        float4 v = s4[i];
        v.x -= lse; v.y -= lse; v.z -= lse; v.w -= lse;
        p4[i] = v;
    }
}

// ---------------- host orchestration ----------------------------------------
extern "C" void kernel_launch(void* const* d_in, const int* in_sizes, int n_in,
                              void* d_out, int out_size) {
    const float* x     = (const float*)d_in[0];
    const float* V     = (const float*)d_in[1];
    const float* Dm    = (const float*)d_in[2];
    const float* eigs  = (const float*)d_in[3];
    const float* fc1_w = (const float*)d_in[4];
    const float* bf1_g = (const float*)d_in[6];
    const float* bf1_b = (const float*)d_in[7];
    const float* W1  = (const float*)d_in[8];
    const float* b1g = (const float*)d_in[10];
    const float* b1b = (const float*)d_in[11];
    const float* W2  = (const float*)d_in[12];
    const float* b2g = (const float*)d_in[14];
    const float* b2b = (const float*)d_in[15];
    const float* W3  = (const float*)d_in[16];
    const float* b3g = (const float*)d_in[18];
    const float* b3b = (const float*)d_in[19];
    const float* fc2_w = (const float*)d_in[20];
    const float* bf2_g = (const float*)d_in[22];
    const float* bf2_b = (const float*)d_in[23];
    const float* fc3_w = (const float*)d_in[24];
    const float* fc3_b = (const float*)d_in[25];

    float* out  = (float*)d_out;
    float* desc = out + (size_t)N_V * N_V;   // outputs: [log_softmax | desc]

    float *acc, *h, *c0, *G;
    cudaGetSymbolAddress((void**)&acc, g_acc);
    cudaGetSymbolAddress((void**)&h,   g_h);
    cudaGetSymbolAddress((void**)&c0,  g_c0);
    cudaGetSymbolAddress((void**)&G,   g_G);

    static bool attr_done = false;
    if (!attr_done) {
        cudaFuncSetAttribute(fc3_kernel, cudaFuncAttributeMaxDynamicSharedMemorySize, SM_TOT);
        cudaFuncSetAttribute(spectral_kernel<64>,  cudaFuncAttributeMaxDynamicSharedMemorySize, (5 * 4096 + 2 * 64 * 64) * 4);
        cudaFuncSetAttribute(spectral_kernel<128>, cudaFuncAttributeMaxDynamicSharedMemorySize, (5 * 4096 + 2 * 64 * 128) * 4);
        cudaFuncSetAttribute(chebout_kernel<64>,  cudaFuncAttributeMaxDynamicSharedMemorySize, 98304);
        cudaFuncSetAttribute(chebout_kernel<128>, cudaFuncAttributeMaxDynamicSharedMemorySize, 98304);
        attr_done = true;
    }

    // independent prep: G = D @ V, fc3_w transpose+fp16
    zero64<<<16, 256>>>(G);
    dmat_kernel<<<125, 256>>>(Dm, V, G);
    split_b_kernel<<<dim3((N_V + 31) / 32, 256 / 32), dim3(32, 32)>>>(fc3_w);

    // fc1 + BN + relu -> h[10000,64]   (bias cancels in BN)
    {
        dim3 g1(1, (N_V + 63) / 64);
        gemm_small<0, 0><<<g1, 256>>>(x, fc1_w, nullptr, acc, N_V, 64, IN_DESC);
        bn_stats<<<64, 256>>>(acc, bf1_g, bf1_b, 64);
        bn_apply<<<(N_V * 64 + 255) / 256, 256>>>(acc, h, 64, N_V * 64);
    }

    // cheb layer 1 (Cout=64)
    zero64<<<16, 256>>>(c0);
    dmat_kernel<<<125, 256>>>(Dm, h, c0);
    spectral_kernel<64><<<1, 512, (5 * 4096 + 2 * 64 * 64) * 4>>>(W1, eigs);
    chebout_kernel<64><<<(N_V + 127) / 128, 256, 98304>>>(h, V, acc);
    bn_stats<<<64, 256>>>(acc, b1g, b1b, 64);
    bn_apply<<<(N_V * 64 + 255) / 256, 256>>>(acc, h, 64, N_V * 64);

    // cheb layer 2 (Cout=64)
    zero64<<<16, 256>>>(c0);
    dmat_kernel<<<125, 256>>>(Dm, h, c0);
    spectral_kernel<64><<<1, 512, (5 * 4096 + 2 * 64 * 64) * 4>>>(W2, eigs);
    chebout_kernel<64><<<(N_V + 127) / 128, 256, 98304>>>(h, V, acc);
    bn_stats<<<64, 256>>>(acc, b2g, b2b, 64);
    bn_apply<<<(N_V * 64 + 255) / 256, 256>>>(acc, h, 64, N_V * 64);

    // cheb layer 3 (Cout=128)
    zero64<<<16, 256>>>(c0);
    dmat_kernel<<<125, 256>>>(Dm, h, c0);
    spectral_kernel<128><<<1, 512, (5 * 4096 + 2 * 64 * 128) * 4>>>(W3, eigs);
    chebout_kernel<128><<<(N_V + 63) / 64, 256, 98304>>>(h, V, acc);
    bn_stats<<<128, 256>>>(acc, b3g, b3b, 128);
    bn_apply<<<(N_V * 128 + 255) / 256, 256>>>(acc, h, 128, N_V * 128);

    // fc2 + BN + relu -> desc
    {
        dim3 g2(256 / 64, (N_V + 63) / 64);
        gemm_small<0, 0><<<g2, 256>>>(h, fc2_w, nullptr, acc, N_V, 256, 128);
        bn_stats<<<256, 256>>>(acc, bf2_g, bf2_b, 256);
        bn_apply<<<(N_V * 256 + 255) / 256, 256>>>(acc, desc, 256, N_V * 256);
    }

    // desc fp16 convert + fc3 (mma.sync fp16 single-pass)
    split_a_kernel<<<(N_V * 64 + 255) / 256, 256>>>(desc);
    {
        dim3 g3((N_V + 127) / 128, (N_V + 127) / 128);
        fc3_kernel<<<g3, 256, SM_TOT>>>(fc3_b, out);
    }

    // in-place row log-softmax
    lsm_kernel<<<N_V, 256>>>(out);
}

// round 9
// speedup vs baseline: 2.2243x; 1.1000x over previous
#include <cuda_runtime.h>
#include <cuda_fp16.h>
#include <math.h>
#include <stdint.h>

#define N_V 10000
#define NSPEC 64
#define IN_DESC 352
#define OUT_DESC 256

// ---------------- scratch (device globals; no allocations allowed) ----------
__device__ float g_acc[N_V * 256];   // pre-BN accumulator (max width 256: fc2)
__device__ float g_h[N_V * 128];     // current activations
__device__ float g_c0[NSPEC * 64];   // D @ X   [64,64]
__device__ float g_G[NSPEC * NSPEC]; // D @ V   [64,64]
__device__ float g_U[64 * 128];      // spectral weight combo [64,Cout]
__device__ float g_Wx[64 * 128];     // direct-X weight combo [64,Cout]
__device__ float g_scale[256];       // BN fused scale/shift
__device__ float g_shift[256];
__device__ __half g_bw[N_V * 256];   // fc3_w transposed [N,K] fp16
__device__ __half g_aw[N_V * 256];   // desc [M,K] fp16

// ---------------- mma.sync + cp.async helpers (base sm_103-legal) -----------
__device__ __forceinline__ uint32_t smem_u32(const void* p) {
    uint32_t a;
    asm("{ .reg .u64 t; cvta.to.shared.u64 t, %1; cvt.u32.u64 %0, t; }" : "=r"(a) : "l"(p));
    return a;
}
#define LDSM_X4(r0, r1, r2, r3, addr) \
    asm volatile("ldmatrix.sync.aligned.m8n8.x4.shared.b16 {%0,%1,%2,%3}, [%4];" \
        : "=r"(r0), "=r"(r1), "=r"(r2), "=r"(r3) : "r"(addr))
#define LDSM_X2(r0, r1, addr) \
    asm volatile("ldmatrix.sync.aligned.m8n8.x2.shared.b16 {%0,%1}, [%2];" \
        : "=r"(r0), "=r"(r1) : "r"(addr))
#define MMA_F16(c, a, b) \
    asm volatile("mma.sync.aligned.m16n8k16.row.col.f32.f16.f16.f32 " \
        "{%0,%1,%2,%3}, {%4,%5,%6,%7}, {%8,%9}, {%0,%1,%2,%3};" \
        : "+f"((c)[0]), "+f"((c)[1]), "+f"((c)[2]), "+f"((c)[3]) \
        : "r"((a)[0]), "r"((a)[1]), "r"((a)[2]), "r"((a)[3]), "r"((b)[0]), "r"((b)[1]))
#define CP_ASYNC16(smaddr, gptr) \
    asm volatile("cp.async.cg.shared.global [%0], [%1], 16;" :: "r"(smaddr), "l"(gptr))
#define CP_COMMIT() asm volatile("cp.async.commit_group;" ::: "memory")
#define CP_WAIT1()  asm volatile("cp.async.wait_group 1;" ::: "memory")
#define CP_WAIT0()  asm volatile("cp.async.wait_group 0;" ::: "memory")

__device__ __forceinline__ uint32_t sw128(uint32_t off) {
    return off ^ ((off >> 3) & 0x70);
}
__device__ __forceinline__ uint32_t packh(__half a, __half b) {
    unsigned short ua = *reinterpret_cast<unsigned short*>(&a);
    unsigned short ub = *reinterpret_cast<unsigned short*>(&b);
    return (uint32_t)ua | ((uint32_t)ub << 16);
}

// FMA-pipe exp: e^x = 2^i * 2^f, degree-6 Taylor for 2^f, exponent bit-add.
__device__ __forceinline__ float fexp(float x) {
    float y = fmaxf(x * 1.4426950408889634f, -120.f);
    float fi = floorf(y);
    float f = y - fi;
    float r = 1.5403530e-4f;
    r = fmaf(r, f, 1.3333558e-3f);
    r = fmaf(r, f, 9.6181291e-3f);
    r = fmaf(r, f, 5.5504109e-2f);
    r = fmaf(r, f, 2.4022651e-1f);
    r = fmaf(r, f, 6.9314718e-1f);
    r = fmaf(r, f, 1.0f);
    return __int_as_float(__float_as_int(r) + ((int)fi << 23));
}

// ---------------- fc3_w pre-transpose + fp16: [K=256,N] -> [N,K] ------------
__global__ void split_b_kernel(const float* __restrict__ W) {
    __shared__ float s[32][33];
    const int tx = threadIdx.x, ty = threadIdx.y;
    const int n0 = blockIdx.x * 32, k0 = blockIdx.y * 32;
    float v = 0.f;
    if (n0 + tx < N_V) v = W[(size_t)(k0 + ty) * N_V + n0 + tx];
    s[ty][tx] = v;
    __syncthreads();
    int n = n0 + ty;
    if (n < N_V) g_bw[(size_t)n * 256 + k0 + tx] = __float2half(s[tx][ty]);
}

// ---------------- desc fp16 convert: [M,K] fp32 -> fp16 ----------------------
__global__ void split_a_kernel(const float* __restrict__ A) {
    int i = blockIdx.x * 256 + threadIdx.x;
    if (i < N_V * 64) {
        float4 f = ((const float4*)A)[i];
        uint2 hv;
        hv.x = packh(__float2half(f.x), __float2half(f.y));
        hv.y = packh(__float2half(f.z), __float2half(f.w));
        ((uint2*)g_aw)[i] = hv;
    }
}

// ---------------- fc3 GEMM: mma.sync fp16, cp.async double-buffered ----------
// C[10000,10000] = A[10000,256] @ B[N,K]^T + bias
// CTA: 128x128 tile, 8 warps (2m x 4n), warp tile 64x32, K chunk 64, 2 stages.
#define SM_A0 0
#define SM_B0 16384
#define SM_A1 32768
#define SM_B1 49152
#define SM_TOT 65536

__global__ __launch_bounds__(256, 2)
void fc3_kernel(const float* __restrict__ bias, float* __restrict__ C) {
    extern __shared__ char smem[];
    const uint32_t sbase = smem_u32(smem);
    const int tid = threadIdx.x;
    const int wid = tid >> 5, lane = tid & 31;
    const int wm = wid >> 2, wn = wid & 3;
    const int row0 = blockIdx.y * 128, col0 = blockIdx.x * 128;

    float acc[4][4][4] = {};

    const int l15 = lane & 15;
    const uint32_t a_row = (uint32_t)(wm * 64 + l15);
    const uint32_t a_halfb = (uint32_t)((lane >> 4) * 16);
    const uint32_t b_row = (uint32_t)(wn * 32 + (l15 & 7));
    const uint32_t b_halfb = (uint32_t)((l15 >> 3) * 16);

    // per-thread load slots: 4 iterations x (1 A + 1 B) cp.async of 16B
    const int lr = tid >> 3, lc = tid & 7;        // covers 32 rows x 8 chunks per it

    auto load_chunk = [&](int kc, int buf) {
        const uint32_t sa = sbase + (buf ? SM_A1 : SM_A0);
        const uint32_t sb = sbase + (buf ? SM_B1 : SM_B0);
        #pragma unroll
        for (int t = 0; t < 4; t++) {
            int r = lr + t * 32;
            uint32_t soff = sw128((uint32_t)(r * 128 + lc * 16));
            int ra = min(row0 + r, N_V - 1);
            const char* ga = (const char*)g_aw + (size_t)ra * 512 + (size_t)kc * 128 + lc * 16;
            CP_ASYNC16(sa + soff, ga);
            int rb = min(col0 + r, N_V - 1);
            const char* gb = (const char*)g_bw + (size_t)rb * 512 + (size_t)kc * 128 + lc * 16;
            CP_ASYNC16(sb + soff, gb);
        }
    };

    load_chunk(0, 0);
    CP_COMMIT();

    #pragma unroll
    for (int kc = 0; kc < 4; kc++) {
        if (kc < 3) {
            load_chunk(kc + 1, (kc + 1) & 1);
            CP_COMMIT();
            CP_WAIT1();
        } else {
            CP_WAIT0();
        }
        __syncthreads();
        const uint32_t sa = sbase + ((kc & 1) ? SM_A1 : SM_A0);
        const uint32_t sb = sbase + ((kc & 1) ? SM_B1 : SM_B0);
        #pragma unroll
        for (int ks = 0; ks < 4; ks++) {
            uint32_t af[4][4], bf[4][2];
            #pragma unroll
            for (int mt = 0; mt < 4; mt++) {
                uint32_t off = sw128((a_row + mt * 16) * 128 + ks * 32 + a_halfb);
                LDSM_X4(af[mt][0], af[mt][1], af[mt][2], af[mt][3], sa + off);
            }
            #pragma unroll
            for (int nt = 0; nt < 4; nt++) {
                uint32_t off = sw128((b_row + nt * 8) * 128 + ks * 32 + b_halfb);
                LDSM_X2(bf[nt][0], bf[nt][1], sb + off);
            }
            #pragma unroll
            for (int mt = 0; mt < 4; mt++)
                #pragma unroll
                for (int nt = 0; nt < 4; nt++)
                    MMA_F16(acc[mt][nt], af[mt], bf[nt]);
        }
        __syncthreads();
    }

    const int r_base = row0 + wm * 64 + (lane >> 2);
    const int c_base = col0 + wn * 32 + ((lane & 3) << 1);
    #pragma unroll
    for (int mt = 0; mt < 4; mt++) {
        #pragma unroll
        for (int nt = 0; nt < 4; nt++) {
            int cc = c_base + nt * 8;
            if (cc >= N_V) continue;
            float2 bb = *(const float2*)(bias + cc);
            int rr = r_base + mt * 16;
            if (rr < N_V) {
                float2 v = make_float2(acc[mt][nt][0] + bb.x, acc[mt][nt][1] + bb.y);
                *(float2*)(C + (size_t)rr * N_V + cc) = v;
            }
            if (rr + 8 < N_V) {
                float2 v = make_float2(acc[mt][nt][2] + bb.x, acc[mt][nt][3] + bb.y);
                *(float2*)(C + (size_t)(rr + 8) * N_V + cc) = v;
            }
        }
    }
}

// ---------------- small GEMM (fc1/fc2): C = A @ B ----------------------------
template<int ACC, int BIAS>
__global__ void gemm_small(const float* __restrict__ A, const float* __restrict__ B,
                           const float* __restrict__ bias, float* __restrict__ C,
                           int M, int Nn, int K) {
    __shared__ float As[16][64];
    __shared__ float Bs[16][64];
    const int tid = threadIdx.x;
    const int ty = tid >> 4, tx = tid & 15;
    const int row0 = blockIdx.y * 64, col0 = blockIdx.x * 64;
    const int arow = tid >> 2, ak = (tid & 3) << 2;
    const int bk = tid >> 4, bcol = (tid & 15) << 2;
    float acc[4][4] = {};
    for (int k0 = 0; k0 < K; k0 += 16) {
        float4 av = make_float4(0.f, 0.f, 0.f, 0.f);
        if (row0 + arow < M)
            av = *(const float4*)(A + (size_t)(row0 + arow) * K + k0 + ak);
        As[ak + 0][arow] = av.x; As[ak + 1][arow] = av.y;
        As[ak + 2][arow] = av.z; As[ak + 3][arow] = av.w;
        float4 bv = *(const float4*)(B + (size_t)(k0 + bk) * Nn + col0 + bcol);
        *(float4*)(&Bs[bk][bcol]) = bv;
        __syncthreads();
        #pragma unroll
        for (int kk = 0; kk < 16; kk++) {
            float a[4], b[4];
            #pragma unroll
            for (int i = 0; i < 4; i++) a[i] = As[kk][ty * 4 + i];
            #pragma unroll
            for (int j = 0; j < 4; j++) b[j] = Bs[kk][tx * 4 + j];
            #pragma unroll
            for (int i = 0; i < 4; i++)
                #pragma unroll
                for (int j = 0; j < 4; j++)
                    acc[i][j] += a[i] * b[j];
        }
        __syncthreads();
    }
    #pragma unroll
    for (int i = 0; i < 4; i++) {
        int r = row0 + ty * 4 + i;
        if (r >= M) continue;
        #pragma unroll
        for (int j = 0; j < 4; j++) {
            int c = col0 + tx * 4 + j;
            float v = acc[i][j];
            if (BIAS) v += bias[c];
            if (ACC) v += C[(size_t)r * Nn + c];
            C[(size_t)r * Nn + c] = v;
        }
    }
}

// ---------------- 64x64 split-K reduce: out += D[64,N_V] @ Z[N_V,64] --------
__global__ void zero64(float* p) { p[blockIdx.x * 256 + threadIdx.x] = 0.f; }

__global__ void dmat_kernel(const float* __restrict__ Dm, const float* __restrict__ Z,
                            float* __restrict__ outp) {
    __shared__ float sD[4][64];
    __shared__ float sZ[4][64];
    const int tid = threadIdx.x;
    const int i4 = (tid >> 4) << 2;
    const int j4 = (tid & 15) << 2;
    float acc[4][4] = {};
    const int nb0 = blockIdx.x * 80;
    for (int nb = 0; nb < 80; nb += 4) {
        const int nbase = nb0 + nb;
        {
            int ii = tid >> 2, nn = tid & 3;
            sD[nn][ii] = Dm[(size_t)ii * N_V + nbase + nn];
            sZ[tid >> 6][tid & 63] = Z[(size_t)(nbase + (tid >> 6)) * 64 + (tid & 63)];
        }
        __syncthreads();
        #pragma unroll
        for (int nn = 0; nn < 4; nn++) {
            float d[4], z[4];
            #pragma unroll
            for (int a = 0; a < 4; a++) d[a] = sD[nn][i4 + a];
            #pragma unroll
            for (int b = 0; b < 4; b++) z[b] = sZ[nn][j4 + b];
            #pragma unroll
            for (int a = 0; a < 4; a++)
                #pragma unroll
                for (int b = 0; b < 4; b++)
                    acc[a][b] += d[a] * z[b];
        }
        __syncthreads();
    }
    #pragma unroll
    for (int a = 0; a < 4; a++)
        #pragma unroll
        for (int b = 0; b < 4; b++)
            atomicAdd(&outp[(i4 + a) * 64 + j4 + b], acc[a][b]);
}

// ---------------- spectral Chebyshev recurrence (one block) ------------------
template<int COUT>
__global__ void spectral_kernel(const float* __restrict__ W,
                                const float* __restrict__ eigs) {
    extern __shared__ float sm[];
    float* G   = sm;
    float* c0  = G + 4096;
    float* bufA = c0 + 4096;
    float* bufB = bufA + 4096;
    float* ck  = bufB + 4096;
    float* U   = ck + 4096;
    float* sW  = U + 64 * COUT;
    __shared__ float e[64];
    const int tid = threadIdx.x;
    const int T = blockDim.x;
    for (int i = tid; i < 4096; i += T) { G[i] = g_G[i]; c0[i] = g_c0[i]; }
    if (tid < 64) e[tid] = eigs[tid];
    __syncthreads();
    for (int i = tid; i < 4096; i += T) { bufA[i] = 0.f; bufB[i] = e[i >> 6] * c0[i]; }
    for (int i = tid; i < 64 * COUT; i += T) sW[i] = W[64 * COUT + i];
    __syncthreads();
    for (int i = tid; i < 64 * COUT; i += T) {
        int r = i / COUT, c = i % COUT;
        float s = 0.f;
        #pragma unroll 8
        for (int m = 0; m < 64; m++) s += bufB[r * 64 + m] * sW[m * COUT + c];
        U[i] = s;
    }
    float* sp = bufA;
    float* sc = bufB;
    for (int k = 1; k <= 4; k++) {
        __syncthreads();
        const float a = (k == 2) ? -1.f : ((k == 4) ? 1.f : 0.f);
        for (int i = tid; i < 4096; i += T) {
            int r = i >> 6, c = i & 63;
            float s = 0.f;
            #pragma unroll 8
            for (int m = 0; m < 64; m++) s += G[r * 64 + m] * sc[m * 64 + c];
            ck[i] = s + a * c0[i];
        }
        __syncthreads();
        for (int i = tid; i < 4096; i += T) sp[i] = 2.f * e[i >> 6] * ck[i] - sp[i];
        for (int i = tid; i < 64 * COUT; i += T) sW[i] = W[(size_t)(k + 1) * 64 * COUT + i];
        __syncthreads();
        for (int i = tid; i < 64 * COUT; i += T) {
            int r = i / COUT, c = i % COUT;
            float s = 0.f;
            #pragma unroll 8
            for (int m = 0; m < 64; m++) s += sp[r * 64 + m] * sW[m * COUT + c];
            U[i] += s;
        }
        float* t = sp; sp = sc; sc = t;
    }
    __syncthreads();
    for (int i = tid; i < 64 * COUT; i += T) {
        g_U[i] = U[i];
        g_Wx[i] = W[i] - W[2 * 64 * COUT + i] + W[4 * 64 * COUT + i];
    }
}

// ---------------- cheb output: out = X @ Wx + V @ U --------------------------
template<int COUT>
__global__ void chebout_kernel(const float* __restrict__ X, const float* __restrict__ Vm,
                               float* __restrict__ outp) {
    constexpr int TPR = COUT / 32;
    constexpr int ROWS = 256 / TPR;
    extern __shared__ float sm[];
    float* sWx = sm;
    float* sU  = sWx + 64 * COUT;
    float* sX  = sU + 64 * COUT;
    float* sV  = sX + ROWS * 64;
    const int tid = threadIdx.x;
    for (int i = tid; i < 64 * COUT; i += 256) { sWx[i] = g_Wx[i]; sU[i] = g_U[i]; }
    const int row0 = blockIdx.x * ROWS;
    for (int i = tid; i < ROWS * 16; i += 256) {
        int r = i >> 4, q = i & 15;
        int gr = row0 + r;
        float4 xv = make_float4(0.f, 0.f, 0.f, 0.f), vv = xv;
        if (gr < N_V) {
            xv = *(const float4*)(X + (size_t)gr * 64 + q * 4);
            vv = *(const float4*)(Vm + (size_t)gr * 64 + q * 4);
        }
        *(float4*)(sX + r * 64 + q * 4) = xv;
        *(float4*)(sV + r * 64 + q * 4) = vv;
    }
    __syncthreads();
    const int lr = tid / TPR;
    const int j0 = (tid % TPR) * 32;
    const int gr = row0 + lr;
    float acc[32] = {};
    #pragma unroll 4
    for (int k = 0; k < 64; k++) {
        float a = sX[lr * 64 + k];
        #pragma unroll
        for (int j = 0; j < 32; j++) acc[j] += a * sWx[k * COUT + j0 + j];
    }
    #pragma unroll 4
    for (int k = 0; k < 64; k++) {
        float v = sV[lr * 64 + k];
        #pragma unroll
        for (int j = 0; j < 32; j++) acc[j] += v * sU[k * COUT + j0 + j];
    }
    if (gr < N_V) {
        float* o = outp + (size_t)gr * COUT + j0;
        #pragma unroll
        for (int j = 0; j < 32; j++) o[j] = acc[j];
    }
}

// ---------------- BatchNorm ---------------------------------------------------
__global__ void bn_stats(const float* __restrict__ X, const float* __restrict__ gam,
                         const float* __restrict__ bet, int C) {
    __shared__ float s1[256], s2v[256];
    const int c = blockIdx.x, tid = threadIdx.x;
    float s = 0.f, s2 = 0.f;
    for (int r = tid; r < N_V; r += 256) {
        float v = X[(size_t)r * C + c];
        s += v; s2 += v * v;
    }
    s1[tid] = s; s2v[tid] = s2;
    __syncthreads();
    for (int st = 128; st > 0; st >>= 1) {
        if (tid < st) { s1[tid] += s1[tid + st]; s2v[tid] += s2v[tid + st]; }
        __syncthreads();
    }
    if (tid == 0) {
        float mean = s1[0] * (1.f / N_V);
        float var = s2v[0] * (1.f / N_V) - mean * mean;
        float istd = rsqrtf(var + 1e-3f);
        float sc = gam[c] * istd;
        g_scale[c] = sc;
        g_shift[c] = bet[c] - mean * sc;
    }
}

__global__ void bn_apply(const float* __restrict__ X, float* __restrict__ Y,
                         int C, int total) {
    int i = blockIdx.x * 256 + threadIdx.x;
    if (i < total) {
        int c = i & (C - 1);
        Y[i] = fmaxf(fmaf(X[i], g_scale[c], g_shift[c]), 0.f);
    }
}

// ---------------- in-place row log-softmax (float4, FMA-pipe exp) -----------
__global__ void lsm_kernel(float* __restrict__ out) {
    __shared__ float srow[N_V];
    __shared__ float red[256];
    const int row = blockIdx.x, tid = threadIdx.x;
    float4* p4 = (float4*)(out + (size_t)row * N_V);
    float4* s4 = (float4*)srow;
    float m = -1e30f;
    for (int i = tid; i < N_V / 4; i += 256) {
        float4 v = p4[i];
        s4[i] = v;
        m = fmaxf(m, fmaxf(fmaxf(v.x, v.y), fmaxf(v.z, v.w)));
    }
    red[tid] = m;
    __syncthreads();
    for (int st = 128; st > 0; st >>= 1) {
        if (tid < st) red[tid] = fmaxf(red[tid], red[tid + st]);
        __syncthreads();
    }
    m = red[0];
    __syncthreads();
    float s = 0.f;
    for (int i = tid; i < N_V / 4; i += 256) {
        float4 v = s4[i];
        s += fexp(v.x - m) + fexp(v.y - m) + fexp(v.z - m) + fexp(v.w - m);
    }
    red[tid] = s;
    __syncthreads();
    for (int st = 128; st > 0; st >>= 1) {
        if (tid < st) red[tid] += red[tid + st];
        __syncthreads();
    }
    float lse = m + logf(red[0]);
    for (int i = tid; i < N_V / 4; i += 256) {
        float4 v = s4[i];
        v.x -= lse; v.y -= lse; v.z -= lse; v.w -= lse;
        p4[i] = v;
    }
}

// ---------------- host orchestration ----------------------------------------
extern "C" void kernel_launch(void* const* d_in, const int* in_sizes, int n_in,
                              void* d_out, int out_size) {
    const float* x     = (const float*)d_in[0];
    const float* V     = (const float*)d_in[1];
    const float* Dm    = (const float*)d_in[2];
    const float* eigs  = (const float*)d_in[3];
    const float* fc1_w = (const float*)d_in[4];
    const float* bf1_g = (const float*)d_in[6];
    const float* bf1_b = (const float*)d_in[7];
    const float* W1  = (const float*)d_in[8];
    const float* b1g = (const float*)d_in[10];
    const float* b1b = (const float*)d_in[11];
    const float* W2  = (const float*)d_in[12];
    const float* b2g = (const float*)d_in[14];
    const float* b2b = (const float*)d_in[15];
    const float* W3  = (const float*)d_in[16];
    const float* b3g = (const float*)d_in[18];
    const float* b3b = (const float*)d_in[19];
    const float* fc2_w = (const float*)d_in[20];
    const float* bf2_g = (const float*)d_in[22];
    const float* bf2_b = (const float*)d_in[23];
    const float* fc3_w = (const float*)d_in[24];
    const float* fc3_b = (const float*)d_in[25];

    float* out  = (float*)d_out;
    float* desc = out + (size_t)N_V * N_V;   // outputs: [log_softmax | desc]

    float *acc, *h, *c0, *G;
    cudaGetSymbolAddress((void**)&acc, g_acc);
    cudaGetSymbolAddress((void**)&h,   g_h);
    cudaGetSymbolAddress((void**)&c0,  g_c0);
    cudaGetSymbolAddress((void**)&G,   g_G);

    static bool attr_done = false;
    if (!attr_done) {
        cudaFuncSetAttribute(fc3_kernel, cudaFuncAttributeMaxDynamicSharedMemorySize, SM_TOT);
        cudaFuncSetAttribute(spectral_kernel<64>,  cudaFuncAttributeMaxDynamicSharedMemorySize, (5 * 4096 + 2 * 64 * 64) * 4);
        cudaFuncSetAttribute(spectral_kernel<128>, cudaFuncAttributeMaxDynamicSharedMemorySize, (5 * 4096 + 2 * 64 * 128) * 4);
        cudaFuncSetAttribute(chebout_kernel<64>,  cudaFuncAttributeMaxDynamicSharedMemorySize, 98304);
        cudaFuncSetAttribute(chebout_kernel<128>, cudaFuncAttributeMaxDynamicSharedMemorySize, 98304);
        attr_done = true;
    }

    // independent prep: G = D @ V, fc3_w transpose+fp16
    zero64<<<16, 256>>>(G);
    dmat_kernel<<<125, 256>>>(Dm, V, G);
    split_b_kernel<<<dim3((N_V + 31) / 32, 256 / 32), dim3(32, 32)>>>(fc3_w);

    // fc1 + BN + relu -> h[10000,64]   (bias cancels in BN)
    {
        dim3 g1(1, (N_V + 63) / 64);
        gemm_small<0, 0><<<g1, 256>>>(x, fc1_w, nullptr, acc, N_V, 64, IN_DESC);
        bn_stats<<<64, 256>>>(acc, bf1_g, bf1_b, 64);
        bn_apply<<<(N_V * 64 + 255) / 256, 256>>>(acc, h, 64, N_V * 64);
    }

    // cheb layer 1 (Cout=64)
    zero64<<<16, 256>>>(c0);
    dmat_kernel<<<125, 256>>>(Dm, h, c0);
    spectral_kernel<64><<<1, 512, (5 * 4096 + 2 * 64 * 64) * 4>>>(W1, eigs);
    chebout_kernel<64><<<(N_V + 127) / 128, 256, 98304>>>(h, V, acc);
    bn_stats<<<64, 256>>>(acc, b1g, b1b, 64);
    bn_apply<<<(N_V * 64 + 255) / 256, 256>>>(acc, h, 64, N_V * 64);

    // cheb layer 2 (Cout=64)
    zero64<<<16, 256>>>(c0);
    dmat_kernel<<<125, 256>>>(Dm, h, c0);
    spectral_kernel<64><<<1, 512, (5 * 4096 + 2 * 64 * 64) * 4>>>(W2, eigs);
    chebout_kernel<64><<<(N_V + 127) / 128, 256, 98304>>>(h, V, acc);
    bn_stats<<<64, 256>>>(acc, b2g, b2b, 64);
    bn_apply<<<(N_V * 64 + 255) / 256, 256>>>(acc, h, 64, N_V * 64);

    // cheb layer 3 (Cout=128)
    zero64<<<16, 256>>>(c0);
    dmat_kernel<<<125, 256>>>(Dm, h, c0);
    spectral_kernel<128><<<1, 512, (5 * 4096 + 2 * 64 * 128) * 4>>>(W3, eigs);
    chebout_kernel<128><<<(N_V + 63) / 64, 256, 98304>>>(h, V, acc);
    bn_stats<<<128, 256>>>(acc, b3g, b3b, 128);
    bn_apply<<<(N_V * 128 + 255) / 256, 256>>>(acc, h, 128, N_V * 128);

    // fc2 + BN + relu -> desc
    {
        dim3 g2(256 / 64, (N_V + 63) / 64);
        gemm_small<0, 0><<<g2, 256>>>(h, fc2_w, nullptr, acc, N_V, 256, 128);
        bn_stats<<<256, 256>>>(acc, bf2_g, bf2_b, 256);
        bn_apply<<<(N_V * 256 + 255) / 256, 256>>>(acc, desc, 256, N_V * 256);
    }

    // desc fp16 convert + fc3 (mma.sync fp16, cp.async pipelined)
    split_a_kernel<<<(N_V * 64 + 255) / 256, 256>>>(desc);
    {
        dim3 g3((N_V + 127) / 128, (N_V + 127) / 128);
        fc3_kernel<<<g3, 256, SM_TOT>>>(fc3_b, out);
    }

    // in-place row log-softmax
    lsm_kernel<<<N_V, 256>>>(out);
}